// round 7
// baseline (speedup 1.0000x reference)
#include <cuda_runtime.h>
#include <stdint.h>

#define BB 2
#define SS 2048
#define DD 1024
#define HH 16
#define NR (BB*SS)            // 4096 rows
#define ATT_SCALE 0.125f      // 1/sqrt(64)

// ---------------- device scratch (no cudaMalloc allowed) ----------------
static __device__ float g_W3[3 * DD * DD];          // concat(Wq,Wk,Wv), tf32-rounded
static __device__ float g_Wo[DD * DD];              // Wo, tf32-rounded
static __device__ float g_b3[3 * DD];
static __device__ float g_X[(size_t)NR * DD];       // x, tf32-rounded
static __device__ float g_QKV[(size_t)NR * 3 * DD]; // (4096, 3072): Q|K|V (tf32-clean)
static __device__ float g_C[(size_t)NR * DD];       // ctx (B,S,D)   (tf32-clean)
static __device__ float g_m[(size_t)32 * SS * 16];  // per-tile row max
static __device__ float g_l[(size_t)32 * SS * 16];  // per-tile row sumexp
static __device__ float g_M[(size_t)32 * SS];       // final row max
static __device__ float g_IL[(size_t)32 * SS];      // final 1/rowsum

// ---------------- tf32 / mma / cp.async helpers ----------------
__device__ __forceinline__ uint32_t f2t(float x) {
    uint32_t r;
    asm("cvt.rna.tf32.f32 %0, %1;" : "=r"(r) : "f"(x));
    return r;
}
__device__ __forceinline__ float f2tf(float x) { return __uint_as_float(f2t(x)); }

__device__ __forceinline__ void mma8(float* c, const uint32_t* a, const uint32_t* b) {
    asm volatile(
        "mma.sync.aligned.m16n8k8.row.col.f32.tf32.tf32.f32 "
        "{%0,%1,%2,%3},{%4,%5,%6,%7},{%8,%9},{%0,%1,%2,%3};"
        : "+f"(c[0]), "+f"(c[1]), "+f"(c[2]), "+f"(c[3])
        : "r"(a[0]), "r"(a[1]), "r"(a[2]), "r"(a[3]), "r"(b[0]), "r"(b[1]));
}
__device__ __forceinline__ void cp16(float* dst, const float* src) {
    uint32_t d = (uint32_t)__cvta_generic_to_shared(dst);
    asm volatile("cp.async.cg.shared.global [%0], [%1], 16;" :: "r"(d), "l"(src));
}
__device__ __forceinline__ void cp_commit() { asm volatile("cp.async.commit_group;"); }
template <int N>
__device__ __forceinline__ void cp_wait() { asm volatile("cp.async.wait_group %0;" :: "n"(N)); }

// ---------------- prep: concat + round weights; round x (float4) ----------------
__global__ void concat_kernel(const float4* __restrict__ Wq, const float4* __restrict__ Wk,
                              const float4* __restrict__ Wv, const float4* __restrict__ Wo,
                              const float* __restrict__ bq, const float* __restrict__ bk,
                              const float* __restrict__ bv) {
    const int i = blockIdx.x * 256 + threadIdx.x;      // float4 index, < DD*DD/4
    float4* w3 = (float4*)g_W3;
    float4* wo = (float4*)g_Wo;
    const int q4 = DD * DD / 4;
    float4 a = Wq[i], b = Wk[i], c = Wv[i], d = Wo[i];
    a.x = f2tf(a.x); a.y = f2tf(a.y); a.z = f2tf(a.z); a.w = f2tf(a.w);
    b.x = f2tf(b.x); b.y = f2tf(b.y); b.z = f2tf(b.z); b.w = f2tf(b.w);
    c.x = f2tf(c.x); c.y = f2tf(c.y); c.z = f2tf(c.z); c.w = f2tf(c.w);
    d.x = f2tf(d.x); d.y = f2tf(d.y); d.z = f2tf(d.z); d.w = f2tf(d.w);
    w3[i] = a; w3[q4 + i] = b; w3[2 * q4 + i] = c; wo[i] = d;
    if (i < DD) {
        g_b3[i]          = bq[i];
        g_b3[DD + i]     = bk[i];
        g_b3[2 * DD + i] = bv[i];
    }
}
__global__ void roundx_kernel(const float4* __restrict__ x) {
    const size_t i = (size_t)blockIdx.x * 256 + threadIdx.x;
    float4 v = x[i];
    v.x = f2tf(v.x); v.y = f2tf(v.y); v.z = f2tf(v.z); v.w = f2tf(v.w);
    ((float4*)g_X)[i] = v;
}

// ---------------- NT GEMM (tf32 tensor, cp.async, BK=32, 3-stage) ----------------
#define G2STG (128*36)   // floats per operand stage
template <bool RND>
__global__ __launch_bounds__(256, 2) void gemm_v6(
    const float* __restrict__ A, const float* __restrict__ Bw,
    const float* __restrict__ bias, float* __restrict__ C,
    int M, int N, int K)
{
    extern __shared__ float sm[];
    float* As = sm;                // [3][128][36]
    float* Bs = sm + 3 * G2STG;    // [3][128][36]

    const int t = threadIdx.x, lane = t & 31, w = t >> 5;
    const int g = lane >> 2, tg = lane & 3;
    const int wm = w & 3, wn = w >> 2;
    const int row0 = blockIdx.y * 128, col0 = blockIdx.x * 128;

    const int lrow = t >> 1, lseg = (t & 1) * 16;
    const float* Ap = A  + (size_t)(row0 + lrow) * K + lseg;
    const float* Bp = Bw + (size_t)(col0 + lrow) * K + lseg;
    float* Asd = As + lrow * 36 + lseg;
    float* Bsd = Bs + lrow * 36 + lseg;

    float acc[2][8][4];
#pragma unroll
    for (int i = 0; i < 2; i++)
#pragma unroll
        for (int j = 0; j < 8; j++)
#pragma unroll
            for (int q = 0; q < 4; q++) acc[i][j][q] = 0.f;

    const int nk = K / 32;
#pragma unroll
    for (int s = 0; s < 2; s++) {
#pragma unroll
        for (int j = 0; j < 4; j++) {
            cp16(Asd + s * G2STG + j * 4, Ap + s * 32 + j * 4);
            cp16(Bsd + s * G2STG + j * 4, Bp + s * 32 + j * 4);
        }
        cp_commit();
    }

    int cur = 0;
    for (int kc = 0; kc < nk; kc++) {
        cp_wait<1>();
        __syncthreads();
        if (kc + 2 < nk) {
            const int s = (cur + 2 >= 3) ? cur - 1 : cur + 2;
            const int k0 = (kc + 2) * 32;
#pragma unroll
            for (int j = 0; j < 4; j++) {
                cp16(Asd + s * G2STG + j * 4, Ap + k0 + j * 4);
                cp16(Bsd + s * G2STG + j * 4, Bp + k0 + j * 4);
            }
        }
        cp_commit();

        const float* a = As + cur * G2STG;
        const float* b = Bs + cur * G2STG;
#pragma unroll
        for (int ks = 0; ks < 32; ks += 8) {
            uint32_t af[2][4], bf[8][2];
#pragma unroll
            for (int mt = 0; mt < 2; mt++) {
                const int r = wm * 32 + mt * 16 + g;
                af[mt][0] = __float_as_uint(a[r * 36 + ks + tg]);
                af[mt][1] = __float_as_uint(a[(r + 8) * 36 + ks + tg]);
                af[mt][2] = __float_as_uint(a[r * 36 + ks + tg + 4]);
                af[mt][3] = __float_as_uint(a[(r + 8) * 36 + ks + tg + 4]);
            }
#pragma unroll
            for (int nt = 0; nt < 8; nt++) {
                const int n = wn * 64 + nt * 8 + g;
                bf[nt][0] = __float_as_uint(b[n * 36 + ks + tg]);
                bf[nt][1] = __float_as_uint(b[n * 36 + ks + tg + 4]);
            }
#pragma unroll
            for (int mt = 0; mt < 2; mt++)
#pragma unroll
                for (int nt = 0; nt < 8; nt++)
                    mma8(acc[mt][nt], af[mt], bf[nt]);
        }
        cur = (cur + 1 >= 3) ? 0 : cur + 1;
    }

#pragma unroll
    for (int mt = 0; mt < 2; mt++) {
        const int r = row0 + wm * 32 + mt * 16 + g;
#pragma unroll
        for (int nt = 0; nt < 8; nt++) {
            const int cc = col0 + wn * 64 + nt * 8 + 2 * tg;
            float2 v0, v1;
            v0.x = acc[mt][nt][0] + bias[cc];
            v0.y = acc[mt][nt][1] + bias[cc + 1];
            v1.x = acc[mt][nt][2] + bias[cc];
            v1.y = acc[mt][nt][3] + bias[cc + 1];
            if (RND) {
                v0.x = f2tf(v0.x); v0.y = f2tf(v0.y);
                v1.x = f2tf(v1.x); v1.y = f2tf(v1.y);
            }
            *(float2*)(C + (size_t)r * N + cc)       = v0;
            *(float2*)(C + (size_t)(r + 8) * N + cc) = v1;
        }
    }
}

// ---------------- scores v6: raw scores + per-tile row stats ----------
__global__ __launch_bounds__(256, 2) void scores_v6(
    const float* __restrict__ QKV, float* __restrict__ attn,
    float* __restrict__ gm, float* __restrict__ gl)
{
    const int kt = blockIdx.x, qt = blockIdx.y, z = blockIdx.z;
    if (kt > qt) return;
    const int b = z >> 4, h = z & 15;

    extern __shared__ float sm[];
    float* Qs = sm;                    // [128][68]
    float* Ks = sm + 128 * 68;         // [128][68]
    float* red_m = sm + 2 * 128 * 68;  // [2][128]
    float* red_l = red_m + 256;        // [2][128]

    const int t = threadIdx.x, lane = t & 31, w = t >> 5;
    const int g = lane >> 2, tg = lane & 3;
    const int wm = w & 3, wn = w >> 2;

    const int lrow = t >> 1, c0s = (t & 1) * 16;
    const float* Qp = QKV + ((size_t)(b * SS) + qt * 128 + lrow) * 3072 + h * 64;
    const float* Kp = QKV + ((size_t)(b * SS) + kt * 128 + lrow) * 3072 + DD + h * 64;
    float* Qsd = Qs + lrow * 68;
    float* Ksd = Ks + lrow * 68;

    // phase 0: k-cols [0,32)
#pragma unroll
    for (int j = 0; j < 4; j++) {
        cp16(Qsd + c0s + j * 4, Qp + c0s + j * 4);
        cp16(Ksd + c0s + j * 4, Kp + c0s + j * 4);
    }
    cp_commit();
    // phase 1: k-cols [32,64)
#pragma unroll
    for (int j = 0; j < 4; j++) {
        cp16(Qsd + 32 + c0s + j * 4, Qp + 32 + c0s + j * 4);
        cp16(Ksd + 32 + c0s + j * 4, Kp + 32 + c0s + j * 4);
    }
    cp_commit();

    float acc[2][8][4];
#pragma unroll
    for (int i = 0; i < 2; i++)
#pragma unroll
        for (int j = 0; j < 8; j++)
#pragma unroll
            for (int q = 0; q < 4; q++) acc[i][j][q] = 0.f;

    cp_wait<1>();
    __syncthreads();

#pragma unroll
    for (int half = 0; half < 2; half++) {
#pragma unroll
        for (int ks0 = 0; ks0 < 32; ks0 += 8) {
            const int ks = half * 32 + ks0;
            uint32_t af[2][4], bf[8][2];
#pragma unroll
            for (int mt = 0; mt < 2; mt++) {
                const int r = wm * 32 + mt * 16 + g;
                af[mt][0] = __float_as_uint(Qs[r * 68 + ks + tg]);
                af[mt][1] = __float_as_uint(Qs[(r + 8) * 68 + ks + tg]);
                af[mt][2] = __float_as_uint(Qs[r * 68 + ks + tg + 4]);
                af[mt][3] = __float_as_uint(Qs[(r + 8) * 68 + ks + tg + 4]);
            }
#pragma unroll
            for (int nt = 0; nt < 8; nt++) {
                const int n = wn * 64 + nt * 8 + g;
                bf[nt][0] = __float_as_uint(Ks[n * 68 + ks + tg]);
                bf[nt][1] = __float_as_uint(Ks[n * 68 + ks + tg + 4]);
            }
#pragma unroll
            for (int mt = 0; mt < 2; mt++)
#pragma unroll
                for (int nt = 0; nt < 8; nt++)
                    mma8(acc[mt][nt], af[mt], bf[nt]);
        }
        if (half == 0) {
            cp_wait<0>();
            __syncthreads();
        }
    }

    // scale + store raw + per-tile stats
#pragma unroll
    for (int mt = 0; mt < 2; mt++) {
        const int rg0 = qt * 128 + wm * 32 + mt * 16 + g;
        const int rg1 = rg0 + 8;
        float mA = -1e30f, mB = -1e30f;
#pragma unroll
        for (int nt = 0; nt < 8; nt++) {
#pragma unroll
            for (int q = 0; q < 4; q++) acc[mt][nt][q] *= ATT_SCALE;
            const int cc = kt * 128 + wn * 64 + nt * 8 + 2 * tg;
            float2 v0, v1;
            v0.x = acc[mt][nt][0]; v0.y = acc[mt][nt][1];
            v1.x = acc[mt][nt][2]; v1.y = acc[mt][nt][3];
            *(float2*)(attn + ((size_t)z * SS + rg0) * SS + cc) = v0;
            *(float2*)(attn + ((size_t)z * SS + rg1) * SS + cc) = v1;
            if (cc     <= rg0) mA = fmaxf(mA, acc[mt][nt][0]);
            if (cc + 1 <= rg0) mA = fmaxf(mA, acc[mt][nt][1]);
            if (cc     <= rg1) mB = fmaxf(mB, acc[mt][nt][2]);
            if (cc + 1 <= rg1) mB = fmaxf(mB, acc[mt][nt][3]);
        }
        mA = fmaxf(mA, __shfl_xor_sync(~0u, mA, 1));
        mA = fmaxf(mA, __shfl_xor_sync(~0u, mA, 2));
        mB = fmaxf(mB, __shfl_xor_sync(~0u, mB, 1));
        mB = fmaxf(mB, __shfl_xor_sync(~0u, mB, 2));
        float lA = 0.f, lB = 0.f;
#pragma unroll
        for (int nt = 0; nt < 8; nt++) {
            const int cc = kt * 128 + wn * 64 + nt * 8 + 2 * tg;
            if (cc     <= rg0) lA += __expf(acc[mt][nt][0] - mA);
            if (cc + 1 <= rg0) lA += __expf(acc[mt][nt][1] - mA);
            if (cc     <= rg1) lB += __expf(acc[mt][nt][2] - mB);
            if (cc + 1 <= rg1) lB += __expf(acc[mt][nt][3] - mB);
        }
        lA += __shfl_xor_sync(~0u, lA, 1); lA += __shfl_xor_sync(~0u, lA, 2);
        lB += __shfl_xor_sync(~0u, lB, 1); lB += __shfl_xor_sync(~0u, lB, 2);
        if (tg == 0) {
            const int rl = wm * 32 + mt * 16 + g;
            red_m[wn * 128 + rl]     = mA;  red_l[wn * 128 + rl]     = lA;
            red_m[wn * 128 + rl + 8] = mB;  red_l[wn * 128 + rl + 8] = lB;
        }
    }
    __syncthreads();
    if (t < 128) {
        float ma = red_m[t], mb = red_m[128 + t];
        float la = red_l[t], lb = red_l[128 + t];
        float Mt = fmaxf(ma, mb);
        float Lt = ((ma > -1e29f) ? la * __expf(ma - Mt) : 0.f)
                 + ((mb > -1e29f) ? lb * __expf(mb - Mt) : 0.f);
        const size_t sidx = ((size_t)z * SS + qt * 128 + t) * 16 + kt;
        gm[sidx] = Mt;
        gl[sidx] = Lt;
    }
}

// ---------------- reduce per-row stats: (M, 1/L) ----------------
__global__ void reduce_stats(const float* __restrict__ gm, const float* __restrict__ gl,
                             float* __restrict__ gM, float* __restrict__ gIL)
{
    const int row = blockIdx.x * 256 + threadIdx.x;     // 0..65535
    const int q = row & (SS - 1);
    const int nt_ = (q >> 7) + 1;
    const float* mrow = gm + (size_t)row * 16;
    const float* lrow = gl + (size_t)row * 16;
    float M = -1e30f;
    for (int k = 0; k < nt_; k++) M = fmaxf(M, mrow[k]);
    float L = 0.f;
    for (int k = 0; k < nt_; k++) L += lrow[k] * __expf(mrow[k] - M);
    gM[row]  = M;
    gIL[row] = 1.0f / L;
}

// ---------------- ctx v6: in-register normalize + attn write + attn@V ----------
#define PSTG (128*68)
#define VSTG (64*72)
__global__ __launch_bounds__(256, 2) void ctx_v6(
    float* __restrict__ attn, const float* __restrict__ QKV,
    const float* __restrict__ gM, const float* __restrict__ gIL,
    float* __restrict__ Cout)
{
    extern __shared__ float sm[];
    float* Ps  = sm;                        // [2][128][68]  (raw scores)
    float* Vs  = sm + 2 * PSTG;             // [2][64][72]
    float* sM  = sm + 2 * PSTG + 2 * VSTG;  // [128]
    float* sIL = sM + 128;                  // [128]

    const int qt = 15 - blockIdx.x;       // reversed: longest blocks first
    const int z = blockIdx.y;
    const int b = z >> 4, h = z & 15;
    const int t = threadIdx.x, lane = t & 31, w = t >> 5;
    const int g = lane >> 2, tg = lane & 3;
    const int wm = w & 3, wn = w >> 2;

    const int prow = t >> 1, pseg = (t & 1) * 32;
    const int vrow = t >> 2, vseg = (t & 3) * 16;
    float* Pp = attn + ((size_t)z * SS + qt * 128 + prow) * SS + pseg;
    const float* Vp = QKV + ((size_t)(b * SS) + vrow) * 3072 + 2 * DD + h * 64 + vseg;
    float* Psd = Ps + prow * 68 + pseg;
    float* Vsd = Vs + vrow * 72 + vseg;

    if (t < 128) {
        sM[t]  = gM[(size_t)z * SS + qt * 128 + t];
        sIL[t] = gIL[(size_t)z * SS + qt * 128 + t];
    }

    const int cnt = 2 * qt + 2;

    float acc[2][4][4];
#pragma unroll
    for (int i = 0; i < 2; i++)
#pragma unroll
        for (int j = 0; j < 4; j++)
#pragma unroll
            for (int q = 0; q < 4; q++) acc[i][j][q] = 0.f;

    // prologue: stage 0 = kt 0
#pragma unroll
    for (int j = 0; j < 8; j++) cp16(Psd + j * 4, Pp + j * 4);
#pragma unroll
    for (int j = 0; j < 4; j++) cp16(Vsd + j * 4, Vp + j * 4);
    cp_commit();
    __syncthreads();   // sM/sIL visible to all

    // hoisted per-warp row stats + attn row pointers
    const int rl0 = wm * 32 + g;              // mt0 rows: rl0, rl0+8 ; mt1: +16,+24
    const float Ma0 = sM[rl0],      iA0 = sIL[rl0];
    const float Mb0 = sM[rl0 + 8],  iB0 = sIL[rl0 + 8];
    const float Ma1 = sM[rl0 + 16], iA1 = sIL[rl0 + 16];
    const float Mb1 = sM[rl0 + 24], iB1 = sIL[rl0 + 24];
    const int ga0 = qt * 128 + rl0, gb0 = ga0 + 8;
    const int ga1 = ga0 + 16,       gb1 = ga0 + 24;
    float* ra0 = attn + ((size_t)z * SS + ga0) * SS;
    float* rb0 = attn + ((size_t)z * SS + gb0) * SS;
    float* ra1 = attn + ((size_t)z * SS + ga1) * SS;
    float* rb1 = attn + ((size_t)z * SS + gb1) * SS;

    for (int kti = 0; kti < cnt; kti++) {
        if (kti + 1 < cnt) {
            const int st = (kti + 1) & 1;
#pragma unroll
            for (int j = 0; j < 8; j++)
                cp16(Psd + st * PSTG + j * 4, Pp + (kti + 1) * 64 + j * 4);
#pragma unroll
            for (int j = 0; j < 4; j++)
                cp16(Vsd + st * VSTG + j * 4, Vp + (size_t)(kti + 1) * 64 * 3072 + j * 4);
        }
        cp_commit();
        cp_wait<1>();
        __syncthreads();

        const float* pp = Ps + (kti & 1) * PSTG;
        const float* vv = Vs + (kti & 1) * VSTG;
#pragma unroll
        for (int ks = 0; ks < 64; ks += 8) {
            const int c0 = kti * 64 + ks + tg;
            const int c1 = c0 + 4;
            uint32_t af[2][4], bf[4][2];
            // mt = 0
            {
                float s0 = pp[rl0 * 68 + ks + tg];
                float s1 = pp[(rl0 + 8) * 68 + ks + tg];
                float s2 = pp[rl0 * 68 + ks + tg + 4];
                float s3 = pp[(rl0 + 8) * 68 + ks + tg + 4];
                float p0 = (c0 <= ga0) ? __expf(s0 - Ma0) * iA0 : 0.f;
                float p1 = (c0 <= gb0) ? __expf(s1 - Mb0) * iB0 : 0.f;
                float p2 = (c1 <= ga0) ? __expf(s2 - Ma0) * iA0 : 0.f;
                float p3 = (c1 <= gb0) ? __expf(s3 - Mb0) * iB0 : 0.f;
                af[0][0] = __float_as_uint(p0); af[0][1] = __float_as_uint(p1);
                af[0][2] = __float_as_uint(p2); af[0][3] = __float_as_uint(p3);
                if (wn == 0) {
                    ra0[c0] = p0; rb0[c0] = p1;
                    ra0[c1] = p2; rb0[c1] = p3;
                }
            }
            // mt = 1
            {
                float s0 = pp[(rl0 + 16) * 68 + ks + tg];
                float s1 = pp[(rl0 + 24) * 68 + ks + tg];
                float s2 = pp[(rl0 + 16) * 68 + ks + tg + 4];
                float s3 = pp[(rl0 + 24) * 68 + ks + tg + 4];
                float p0 = (c0 <= ga1) ? __expf(s0 - Ma1) * iA1 : 0.f;
                float p1 = (c0 <= gb1) ? __expf(s1 - Mb1) * iB1 : 0.f;
                float p2 = (c1 <= ga1) ? __expf(s2 - Ma1) * iA1 : 0.f;
                float p3 = (c1 <= gb1) ? __expf(s3 - Mb1) * iB1 : 0.f;
                af[1][0] = __float_as_uint(p0); af[1][1] = __float_as_uint(p1);
                af[1][2] = __float_as_uint(p2); af[1][3] = __float_as_uint(p3);
                if (wn == 0) {
                    ra1[c0] = p0; rb1[c0] = p1;
                    ra1[c1] = p2; rb1[c1] = p3;
                }
            }
#pragma unroll
            for (int nt = 0; nt < 4; nt++) {
                const int n = wn * 32 + nt * 8 + g;
                bf[nt][0] = __float_as_uint(vv[(ks + tg) * 72 + n]);
                bf[nt][1] = __float_as_uint(vv[(ks + tg + 4) * 72 + n]);
            }
#pragma unroll
            for (int mt = 0; mt < 2; mt++)
#pragma unroll
                for (int nt = 0; nt < 4; nt++)
                    mma8(acc[mt][nt], af[mt], bf[nt]);
        }
        __syncthreads();
    }

    // zero-fill the strict upper region of these rows
    {
        const float4 z4 = make_float4(0.f, 0.f, 0.f, 0.f);
        for (int c = cnt * 64; c < SS; c += 64) {
#pragma unroll
            for (int j = 0; j < 8; j++)
                *(float4*)(Pp + c + j * 4) = z4;
        }
    }

#pragma unroll
    for (int mt = 0; mt < 2; mt++) {
        const int qrow = qt * 128 + wm * 32 + mt * 16 + g;
#pragma unroll
        for (int nt = 0; nt < 4; nt++) {
            const int cc = h * 64 + wn * 32 + nt * 8 + 2 * tg;
            float2 v0, v1;
            v0.x = f2tf(acc[mt][nt][0]); v0.y = f2tf(acc[mt][nt][1]);
            v1.x = f2tf(acc[mt][nt][2]); v1.y = f2tf(acc[mt][nt][3]);
            *(float2*)(Cout + ((size_t)(b * SS) + qrow) * DD + cc)     = v0;
            *(float2*)(Cout + ((size_t)(b * SS) + qrow + 8) * DD + cc) = v1;
        }
    }
}

// ---------------- launch ----------------
extern "C" void kernel_launch(void* const* d_in, const int* in_sizes, int n_in,
                              void* d_out, int out_size)
{
    const float* x  = (const float*)d_in[0];
    const float* Wq = (const float*)d_in[1];
    const float* bq = (const float*)d_in[2];
    const float* Wk = (const float*)d_in[3];
    const float* bk = (const float*)d_in[4];
    const float* Wv = (const float*)d_in[5];
    const float* bv = (const float*)d_in[6];
    const float* Wo = (const float*)d_in[7];
    const float* bo = (const float*)d_in[8];

    float* out  = (float*)d_out;
    float* attn = out + (size_t)NR * DD;   // tuple order: (out, attn)

    float *pW3, *pWo, *pb3, *pX, *pQKV, *pC, *pm, *pl, *pM, *pIL;
    cudaGetSymbolAddress((void**)&pW3,  g_W3);
    cudaGetSymbolAddress((void**)&pWo,  g_Wo);
    cudaGetSymbolAddress((void**)&pb3,  g_b3);
    cudaGetSymbolAddress((void**)&pX,   g_X);
    cudaGetSymbolAddress((void**)&pQKV, g_QKV);
    cudaGetSymbolAddress((void**)&pC,   g_C);
    cudaGetSymbolAddress((void**)&pm,   g_m);
    cudaGetSymbolAddress((void**)&pl,   g_l);
    cudaGetSymbolAddress((void**)&pM,   g_M);
    cudaGetSymbolAddress((void**)&pIL,  g_IL);

    const int gemm_smem   = 3 * G2STG * 2 * 4;                 // 110592
    const int scores_smem = (2 * 128 * 68 + 512) * 4;          // 71680
    const int ctx_smem    = (2 * PSTG + 2 * VSTG + 256) * 4;   // 107520
    cudaFuncSetAttribute(gemm_v6<true>,  cudaFuncAttributeMaxDynamicSharedMemorySize, gemm_smem);
    cudaFuncSetAttribute(gemm_v6<false>, cudaFuncAttributeMaxDynamicSharedMemorySize, gemm_smem);
    cudaFuncSetAttribute(scores_v6,      cudaFuncAttributeMaxDynamicSharedMemorySize, scores_smem);
    cudaFuncSetAttribute(ctx_v6,         cudaFuncAttributeMaxDynamicSharedMemorySize, ctx_smem);

    // 1) prep
    concat_kernel<<<(DD * DD / 4) / 256, 256>>>(
        (const float4*)Wq, (const float4*)Wk, (const float4*)Wv, (const float4*)Wo,
        bq, bk, bv);
    roundx_kernel<<<((size_t)NR * DD / 4) / 256, 256>>>((const float4*)x);

    // 2) fused QKV projection (stores tf32-rounded outputs)
    gemm_v6<true><<<dim3(3072 / 128, NR / 128), 256, gemm_smem>>>(pX, pW3, pb3, pQKV, NR, 3072, DD);

    // 3) raw causal scores + per-tile stats
    scores_v6<<<dim3(SS / 128, SS / 128, BB * HH), 256, scores_smem>>>(pQKV, attn, pm, pl);

    // 4) fold stats -> per-row (M, 1/L)
    reduce_stats<<<(32 * SS) / 256, 256>>>(pm, pl, pM, pIL);

    // 5) fused normalize + attn write + ctx = attn @ V
    ctx_v6<<<dim3(SS / 128, BB * HH), 256, ctx_smem>>>(attn, pQKV, pM, pIL, pC);

    // 6) output projection (exact fp32 epilogue)
    gemm_v6<false><<<dim3(DD / 128, NR / 128), 256, gemm_smem>>>(pC, pWo, bo, out, NR, DD, DD);
}

// round 8
// speedup vs baseline: 1.1004x; 1.1004x over previous
#include <cuda_runtime.h>
#include <stdint.h>

#define BB 2
#define SS 2048
#define DD 1024
#define HH 16
#define NR (BB*SS)            // 4096 rows
#define ATT_SCALE 0.125f      // 1/sqrt(64)

// ---------------- device scratch (no cudaMalloc allowed) ----------------
static __device__ float g_W3[3 * DD * DD];          // concat(Wq,Wk,Wv), tf32-rounded
static __device__ float g_Wo[DD * DD];              // Wo, tf32-rounded
static __device__ float g_b3[3 * DD];
static __device__ float g_X[(size_t)NR * DD];       // x, tf32-rounded
static __device__ float g_QKV[(size_t)NR * 3 * DD]; // (4096, 3072): Q|K|V (tf32-clean)
static __device__ float g_C[(size_t)NR * DD];       // ctx (B,S,D)   (tf32-clean)
static __device__ float g_l[(size_t)32 * SS * 16];  // per-tile row sum of exp(s)
static __device__ float g_IL[(size_t)32 * SS];      // final 1/rowsum

// ---------------- tf32 / mma / cp.async helpers ----------------
__device__ __forceinline__ uint32_t f2t(float x) {
    uint32_t r;
    asm("cvt.rna.tf32.f32 %0, %1;" : "=r"(r) : "f"(x));
    return r;
}
__device__ __forceinline__ float f2tf(float x) { return __uint_as_float(f2t(x)); }

__device__ __forceinline__ void mma8(float* c, const uint32_t* a, const uint32_t* b) {
    asm volatile(
        "mma.sync.aligned.m16n8k8.row.col.f32.tf32.tf32.f32 "
        "{%0,%1,%2,%3},{%4,%5,%6,%7},{%8,%9},{%0,%1,%2,%3};"
        : "+f"(c[0]), "+f"(c[1]), "+f"(c[2]), "+f"(c[3])
        : "r"(a[0]), "r"(a[1]), "r"(a[2]), "r"(a[3]), "r"(b[0]), "r"(b[1]));
}
__device__ __forceinline__ void cp16(float* dst, const float* src) {
    uint32_t d = (uint32_t)__cvta_generic_to_shared(dst);
    asm volatile("cp.async.cg.shared.global [%0], [%1], 16;" :: "r"(d), "l"(src));
}
__device__ __forceinline__ void cp_commit() { asm volatile("cp.async.commit_group;"); }
template <int N>
__device__ __forceinline__ void cp_wait() { asm volatile("cp.async.wait_group %0;" :: "n"(N)); }

// ---------------- prep: concat + round weights; round x (float4) ----------------
__global__ void concat_kernel(const float4* __restrict__ Wq, const float4* __restrict__ Wk,
                              const float4* __restrict__ Wv, const float4* __restrict__ Wo,
                              const float* __restrict__ bq, const float* __restrict__ bk,
                              const float* __restrict__ bv) {
    const int i = blockIdx.x * 256 + threadIdx.x;      // float4 index, < DD*DD/4
    float4* w3 = (float4*)g_W3;
    float4* wo = (float4*)g_Wo;
    const int q4 = DD * DD / 4;
    float4 a = Wq[i], b = Wk[i], c = Wv[i], d = Wo[i];
    a.x = f2tf(a.x); a.y = f2tf(a.y); a.z = f2tf(a.z); a.w = f2tf(a.w);
    b.x = f2tf(b.x); b.y = f2tf(b.y); b.z = f2tf(b.z); b.w = f2tf(b.w);
    c.x = f2tf(c.x); c.y = f2tf(c.y); c.z = f2tf(c.z); c.w = f2tf(c.w);
    d.x = f2tf(d.x); d.y = f2tf(d.y); d.z = f2tf(d.z); d.w = f2tf(d.w);
    w3[i] = a; w3[q4 + i] = b; w3[2 * q4 + i] = c; wo[i] = d;
    if (i < DD) {
        g_b3[i]          = bq[i];
        g_b3[DD + i]     = bk[i];
        g_b3[2 * DD + i] = bv[i];
    }
}
__global__ void roundx_kernel(const float4* __restrict__ x) {
    const size_t i = (size_t)blockIdx.x * 256 + threadIdx.x;
    float4 v = x[i];
    v.x = f2tf(v.x); v.y = f2tf(v.y); v.z = f2tf(v.z); v.w = f2tf(v.w);
    ((float4*)g_X)[i] = v;
}

// ---------------- NT GEMM (tf32 tensor, cp.async 4-stage, BK=16) -- R6 proven ----
#define GSTG 2560   // 128*20 floats per stage per operand
template <bool RND>
__global__ __launch_bounds__(256, 2) void gemm_v3(
    const float* __restrict__ A, const float* __restrict__ Bw,
    const float* __restrict__ bias, float* __restrict__ C,
    int M, int N, int K)
{
    extern __shared__ float sm[];
    float* As = sm;               // [4][128][20]
    float* Bs = sm + 4 * GSTG;    // [4][128][20]

    const int t = threadIdx.x, lane = t & 31, w = t >> 5;
    const int g = lane >> 2, tg = lane & 3;
    const int wm = w & 3, wn = w >> 2;
    const int row0 = blockIdx.y * 128, col0 = blockIdx.x * 128;

    const int lrow = t >> 1, lseg = (t & 1) * 8;
    const float* Ap = A  + (size_t)(row0 + lrow) * K + lseg;
    const float* Bp = Bw + (size_t)(col0 + lrow) * K + lseg;
    float* Asd = As + lrow * 20 + lseg;
    float* Bsd = Bs + lrow * 20 + lseg;

    float acc[2][8][4];
#pragma unroll
    for (int i = 0; i < 2; i++)
#pragma unroll
        for (int j = 0; j < 8; j++)
#pragma unroll
            for (int q = 0; q < 4; q++) acc[i][j][q] = 0.f;

    const int nk = K / 16;
#pragma unroll
    for (int s = 0; s < 3; s++) {
        cp16(Asd + s * GSTG, Ap + s * 16);
        cp16(Asd + s * GSTG + 4, Ap + s * 16 + 4);
        cp16(Bsd + s * GSTG, Bp + s * 16);
        cp16(Bsd + s * GSTG + 4, Bp + s * 16 + 4);
        cp_commit();
    }

    for (int kc = 0; kc < nk; kc++) {
        cp_wait<2>();
        __syncthreads();
        if (kc + 3 < nk) {
            const int s = (kc + 3) & 3;
            const int k0 = (kc + 3) * 16;
            cp16(Asd + s * GSTG, Ap + k0);
            cp16(Asd + s * GSTG + 4, Ap + k0 + 4);
            cp16(Bsd + s * GSTG, Bp + k0);
            cp16(Bsd + s * GSTG + 4, Bp + k0 + 4);
        }
        cp_commit();

        const float* a = As + (kc & 3) * GSTG;
        const float* b = Bs + (kc & 3) * GSTG;
#pragma unroll
        for (int ks = 0; ks < 16; ks += 8) {
            uint32_t af[2][4], bf[8][2];
#pragma unroll
            for (int mt = 0; mt < 2; mt++) {
                const int r = wm * 32 + mt * 16 + g;
                af[mt][0] = __float_as_uint(a[r * 20 + ks + tg]);
                af[mt][1] = __float_as_uint(a[(r + 8) * 20 + ks + tg]);
                af[mt][2] = __float_as_uint(a[r * 20 + ks + tg + 4]);
                af[mt][3] = __float_as_uint(a[(r + 8) * 20 + ks + tg + 4]);
            }
#pragma unroll
            for (int nt = 0; nt < 8; nt++) {
                const int n = wn * 64 + nt * 8 + g;
                bf[nt][0] = __float_as_uint(b[n * 20 + ks + tg]);
                bf[nt][1] = __float_as_uint(b[n * 20 + ks + tg + 4]);
            }
#pragma unroll
            for (int mt = 0; mt < 2; mt++)
#pragma unroll
                for (int nt = 0; nt < 8; nt++)
                    mma8(acc[mt][nt], af[mt], bf[nt]);
        }
    }

#pragma unroll
    for (int mt = 0; mt < 2; mt++) {
        const int r = row0 + wm * 32 + mt * 16 + g;
#pragma unroll
        for (int nt = 0; nt < 8; nt++) {
            const int cc = col0 + wn * 64 + nt * 8 + 2 * tg;
            float2 v0, v1;
            v0.x = acc[mt][nt][0] + bias[cc];
            v0.y = acc[mt][nt][1] + bias[cc + 1];
            v1.x = acc[mt][nt][2] + bias[cc];
            v1.y = acc[mt][nt][3] + bias[cc + 1];
            if (RND) {
                v0.x = f2tf(v0.x); v0.y = f2tf(v0.y);
                v1.x = f2tf(v1.x); v1.y = f2tf(v1.y);
            }
            *(float2*)(C + (size_t)r * N + cc)       = v0;
            *(float2*)(C + (size_t)(r + 8) * N + cc) = v1;
        }
    }
}

// ---------------- scores v7: pipelined scores + cheap row sum of exp(s) ----------
__global__ __launch_bounds__(256, 2) void scores_v7(
    const float* __restrict__ QKV, float* __restrict__ attn, float* __restrict__ gl)
{
    const int kt = blockIdx.x, qt = blockIdx.y, z = blockIdx.z;
    if (kt > qt) return;
    const int b = z >> 4, h = z & 15;

    extern __shared__ float sm[];
    float* Qs = sm;                   // [128][68]
    float* Ks = sm + 128 * 68;        // [128][68]
    float* red_l = sm + 2 * 128 * 68; // [2][128]

    const int t = threadIdx.x, lane = t & 31, w = t >> 5;
    const int g = lane >> 2, tg = lane & 3;
    const int wm = w & 3, wn = w >> 2;

    const int lrow = t >> 1, c0s = (t & 1) * 16;
    const float* Qp = QKV + ((size_t)(b * SS) + qt * 128 + lrow) * 3072 + h * 64;
    const float* Kp = QKV + ((size_t)(b * SS) + kt * 128 + lrow) * 3072 + DD + h * 64;
    float* Qsd = Qs + lrow * 68;
    float* Ksd = Ks + lrow * 68;

    // phase 0: k-cols [0,32)
#pragma unroll
    for (int j = 0; j < 4; j++) {
        cp16(Qsd + c0s + j * 4, Qp + c0s + j * 4);
        cp16(Ksd + c0s + j * 4, Kp + c0s + j * 4);
    }
    cp_commit();
    // phase 1: k-cols [32,64)
#pragma unroll
    for (int j = 0; j < 4; j++) {
        cp16(Qsd + 32 + c0s + j * 4, Qp + 32 + c0s + j * 4);
        cp16(Ksd + 32 + c0s + j * 4, Kp + 32 + c0s + j * 4);
    }
    cp_commit();

    float acc[2][8][4];
#pragma unroll
    for (int i = 0; i < 2; i++)
#pragma unroll
        for (int j = 0; j < 8; j++)
#pragma unroll
            for (int q = 0; q < 4; q++) acc[i][j][q] = 0.f;

    cp_wait<1>();
    __syncthreads();

#pragma unroll
    for (int half = 0; half < 2; half++) {
#pragma unroll
        for (int ks0 = 0; ks0 < 32; ks0 += 8) {
            const int ks = half * 32 + ks0;
            uint32_t af[2][4], bf[8][2];
#pragma unroll
            for (int mt = 0; mt < 2; mt++) {
                const int r = wm * 32 + mt * 16 + g;
                af[mt][0] = __float_as_uint(Qs[r * 68 + ks + tg]);
                af[mt][1] = __float_as_uint(Qs[(r + 8) * 68 + ks + tg]);
                af[mt][2] = __float_as_uint(Qs[r * 68 + ks + tg + 4]);
                af[mt][3] = __float_as_uint(Qs[(r + 8) * 68 + ks + tg + 4]);
            }
#pragma unroll
            for (int nt = 0; nt < 8; nt++) {
                const int n = wn * 64 + nt * 8 + g;
                bf[nt][0] = __float_as_uint(Ks[n * 68 + ks + tg]);
                bf[nt][1] = __float_as_uint(Ks[n * 68 + ks + tg + 4]);
            }
#pragma unroll
            for (int mt = 0; mt < 2; mt++)
#pragma unroll
                for (int nt = 0; nt < 8; nt++)
                    mma8(acc[mt][nt], af[mt], bf[nt]);
        }
        if (half == 0) {
            cp_wait<0>();
            __syncthreads();
        }
    }

    // scale in place, store raw scores, accumulate per-tile row sum of exp(s)
#pragma unroll
    for (int mt = 0; mt < 2; mt++) {
        const int rg0 = qt * 128 + wm * 32 + mt * 16 + g;
        const int rg1 = rg0 + 8;
        float lA = 0.f, lB = 0.f;
#pragma unroll
        for (int nt = 0; nt < 8; nt++) {
#pragma unroll
            for (int q = 0; q < 4; q++) acc[mt][nt][q] *= ATT_SCALE;
            const int cc = kt * 128 + wn * 64 + nt * 8 + 2 * tg;
            float2 v0, v1;
            v0.x = acc[mt][nt][0]; v0.y = acc[mt][nt][1];
            v1.x = acc[mt][nt][2]; v1.y = acc[mt][nt][3];
            *(float2*)(attn + ((size_t)z * SS + rg0) * SS + cc) = v0;
            *(float2*)(attn + ((size_t)z * SS + rg1) * SS + cc) = v1;
        }
        if (kt < qt) {
            // fully inside causal region: unpredicated
#pragma unroll
            for (int nt = 0; nt < 8; nt++) {
                lA += __expf(acc[mt][nt][0]) + __expf(acc[mt][nt][1]);
                lB += __expf(acc[mt][nt][2]) + __expf(acc[mt][nt][3]);
            }
        } else {
            // diagonal tile: predicated
#pragma unroll
            for (int nt = 0; nt < 8; nt++) {
                const int cc = kt * 128 + wn * 64 + nt * 8 + 2 * tg;
                if (cc     <= rg0) lA += __expf(acc[mt][nt][0]);
                if (cc + 1 <= rg0) lA += __expf(acc[mt][nt][1]);
                if (cc     <= rg1) lB += __expf(acc[mt][nt][2]);
                if (cc + 1 <= rg1) lB += __expf(acc[mt][nt][3]);
            }
        }
        lA += __shfl_xor_sync(~0u, lA, 1); lA += __shfl_xor_sync(~0u, lA, 2);
        lB += __shfl_xor_sync(~0u, lB, 1); lB += __shfl_xor_sync(~0u, lB, 2);
        if (tg == 0) {
            const int rl = wm * 32 + mt * 16 + g;
            red_l[wn * 128 + rl]     = lA;
            red_l[wn * 128 + rl + 8] = lB;
        }
    }
    __syncthreads();
    if (t < 128) {
        gl[((size_t)z * SS + qt * 128 + t) * 16 + kt] = red_l[t] + red_l[128 + t];
    }
}

// ---------------- reduce per-row sums -> 1/L ----------------
__global__ void reduce_stats(const float* __restrict__ gl, float* __restrict__ gIL)
{
    const int row = blockIdx.x * 256 + threadIdx.x;     // 0..65535
    const int q = row & (SS - 1);
    const int nt_ = (q >> 7) + 1;
    const float* lrow = gl + (size_t)row * 16;
    float L = 0.f;
    for (int k = 0; k < nt_; k++) L += lrow[k];
    gIL[row] = 1.0f / L;
}

// ---------------- ctx v7: in-register p=exp(s)*iL + attn write + attn@V ----------
#define PSTG (128*68)
#define VSTG (64*72)
__global__ __launch_bounds__(256, 2) void ctx_v7(
    float* __restrict__ attn, const float* __restrict__ QKV,
    const float* __restrict__ gIL, float* __restrict__ Cout)
{
    extern __shared__ float sm[];
    float* Ps  = sm;                        // [2][128][68] raw scores
    float* Vs  = sm + 2 * PSTG;             // [2][64][72]
    float* sIL = sm + 2 * PSTG + 2 * VSTG;  // [128]

    const int qt = 15 - blockIdx.x;       // reversed: longest blocks first
    const int z = blockIdx.y;
    const int b = z >> 4, h = z & 15;
    const int t = threadIdx.x, lane = t & 31, w = t >> 5;
    const int g = lane >> 2, tg = lane & 3;
    const int wm = w & 3, wn = w >> 2;

    const int prow = t >> 1, pseg = (t & 1) * 32;
    const int vrow = t >> 2, vseg = (t & 3) * 16;
    float* Pp = attn + ((size_t)z * SS + qt * 128 + prow) * SS + pseg;
    const float* Vp = QKV + ((size_t)(b * SS) + vrow) * 3072 + 2 * DD + h * 64 + vseg;
    float* Psd = Ps + prow * 68 + pseg;
    float* Vsd = Vs + vrow * 72 + vseg;

    if (t < 128) sIL[t] = gIL[(size_t)z * SS + qt * 128 + t];

    const int cnt = 2 * qt + 2;

    float acc[2][4][4];
#pragma unroll
    for (int i = 0; i < 2; i++)
#pragma unroll
        for (int j = 0; j < 4; j++)
#pragma unroll
            for (int q = 0; q < 4; q++) acc[i][j][q] = 0.f;

    // prologue: stage 0 = chunk 0
#pragma unroll
    for (int j = 0; j < 8; j++) cp16(Psd + j * 4, Pp + j * 4);
#pragma unroll
    for (int j = 0; j < 4; j++) cp16(Vsd + j * 4, Vp + j * 4);
    cp_commit();
    __syncthreads();   // sIL visible

    const int rl0 = wm * 32 + g;
    const float iA0 = sIL[rl0],      iB0 = sIL[rl0 + 8];
    const float iA1 = sIL[rl0 + 16], iB1 = sIL[rl0 + 24];
    const int ga0 = qt * 128 + rl0, gb0 = ga0 + 8;
    const int ga1 = ga0 + 16,       gb1 = ga0 + 24;
    float* ra0 = attn + ((size_t)z * SS + ga0) * SS;
    float* rb0 = attn + ((size_t)z * SS + gb0) * SS;
    float* ra1 = attn + ((size_t)z * SS + ga1) * SS;
    float* rb1 = attn + ((size_t)z * SS + gb1) * SS;

    for (int kti = 0; kti < cnt; kti++) {
        if (kti + 1 < cnt) {
            const int st = (kti + 1) & 1;
#pragma unroll
            for (int j = 0; j < 8; j++)
                cp16(Psd + st * PSTG + j * 4, Pp + (kti + 1) * 64 + j * 4);
#pragma unroll
            for (int j = 0; j < 4; j++)
                cp16(Vsd + st * VSTG + j * 4, Vp + (size_t)(kti + 1) * 64 * 3072 + j * 4);
        }
        cp_commit();
        cp_wait<1>();
        __syncthreads();

        const float* pp = Ps + (kti & 1) * PSTG;
        const float* vv = Vs + (kti & 1) * VSTG;
        // chunks fully below the diagonal for every row of this tile: no masking
        const bool safe = (kti * 64 + 64 <= qt * 128);
        const int la0 = safe ? 0x7FFFFFF0 : ga0;
        const int lb0 = safe ? 0x7FFFFFF0 : gb0;
        const int la1 = safe ? 0x7FFFFFF0 : ga1;
        const int lb1 = safe ? 0x7FFFFFF0 : gb1;
#pragma unroll
        for (int ks = 0; ks < 64; ks += 8) {
            const int c0 = kti * 64 + ks + tg;
            const int c1 = c0 + 4;
            uint32_t af[2][4], bf[4][2];
            // mt = 0 (rows ga0, gb0)
            {
                float p0 = (c0 <= la0) ? __expf(pp[rl0 * 68 + ks + tg]) * iA0 : 0.f;
                float p1 = (c0 <= lb0) ? __expf(pp[(rl0 + 8) * 68 + ks + tg]) * iB0 : 0.f;
                float p2 = (c1 <= la0) ? __expf(pp[rl0 * 68 + ks + tg + 4]) * iA0 : 0.f;
                float p3 = (c1 <= lb0) ? __expf(pp[(rl0 + 8) * 68 + ks + tg + 4]) * iB0 : 0.f;
                af[0][0] = __float_as_uint(p0); af[0][1] = __float_as_uint(p1);
                af[0][2] = __float_as_uint(p2); af[0][3] = __float_as_uint(p3);
                if (wn == 0) {
                    ra0[c0] = p0; rb0[c0] = p1;
                    ra0[c1] = p2; rb0[c1] = p3;
                }
            }
            // mt = 1 (rows ga1, gb1)
            {
                float p0 = (c0 <= la1) ? __expf(pp[(rl0 + 16) * 68 + ks + tg]) * iA1 : 0.f;
                float p1 = (c0 <= lb1) ? __expf(pp[(rl0 + 24) * 68 + ks + tg]) * iB1 : 0.f;
                float p2 = (c1 <= la1) ? __expf(pp[(rl0 + 16) * 68 + ks + tg + 4]) * iA1 : 0.f;
                float p3 = (c1 <= lb1) ? __expf(pp[(rl0 + 24) * 68 + ks + tg + 4]) * iB1 : 0.f;
                af[1][0] = __float_as_uint(p0); af[1][1] = __float_as_uint(p1);
                af[1][2] = __float_as_uint(p2); af[1][3] = __float_as_uint(p3);
                if (wn == 0) {
                    ra1[c0] = p0; rb1[c0] = p1;
                    ra1[c1] = p2; rb1[c1] = p3;
                }
            }
#pragma unroll
            for (int nt = 0; nt < 4; nt++) {
                const int n = wn * 32 + nt * 8 + g;
                bf[nt][0] = __float_as_uint(vv[(ks + tg) * 72 + n]);
                bf[nt][1] = __float_as_uint(vv[(ks + tg + 4) * 72 + n]);
            }
#pragma unroll
            for (int mt = 0; mt < 2; mt++)
#pragma unroll
                for (int nt = 0; nt < 4; nt++)
                    mma8(acc[mt][nt], af[mt], bf[nt]);
        }
        __syncthreads();
    }

    // zero-fill strict upper region of these rows
    {
        const float4 z4 = make_float4(0.f, 0.f, 0.f, 0.f);
        for (int c = cnt * 64; c < SS; c += 64) {
#pragma unroll
            for (int j = 0; j < 8; j++)
                *(float4*)(Pp + c + j * 4) = z4;
        }
    }

#pragma unroll
    for (int mt = 0; mt < 2; mt++) {
        const int qrow = qt * 128 + wm * 32 + mt * 16 + g;
#pragma unroll
        for (int nt = 0; nt < 4; nt++) {
            const int cc = h * 64 + wn * 32 + nt * 8 + 2 * tg;
            float2 v0, v1;
            v0.x = f2tf(acc[mt][nt][0]); v0.y = f2tf(acc[mt][nt][1]);
            v1.x = f2tf(acc[mt][nt][2]); v1.y = f2tf(acc[mt][nt][3]);
            *(float2*)(Cout + ((size_t)(b * SS) + qrow) * DD + cc)     = v0;
            *(float2*)(Cout + ((size_t)(b * SS) + qrow + 8) * DD + cc) = v1;
        }
    }
}

// ---------------- launch ----------------
extern "C" void kernel_launch(void* const* d_in, const int* in_sizes, int n_in,
                              void* d_out, int out_size)
{
    const float* x  = (const float*)d_in[0];
    const float* Wq = (const float*)d_in[1];
    const float* bq = (const float*)d_in[2];
    const float* Wk = (const float*)d_in[3];
    const float* bk = (const float*)d_in[4];
    const float* Wv = (const float*)d_in[5];
    const float* bv = (const float*)d_in[6];
    const float* Wo = (const float*)d_in[7];
    const float* bo = (const float*)d_in[8];

    float* out  = (float*)d_out;
    float* attn = out + (size_t)NR * DD;   // tuple order: (out, attn)

    float *pW3, *pWo, *pb3, *pX, *pQKV, *pC, *pl, *pIL;
    cudaGetSymbolAddress((void**)&pW3,  g_W3);
    cudaGetSymbolAddress((void**)&pWo,  g_Wo);
    cudaGetSymbolAddress((void**)&pb3,  g_b3);
    cudaGetSymbolAddress((void**)&pX,   g_X);
    cudaGetSymbolAddress((void**)&pQKV, g_QKV);
    cudaGetSymbolAddress((void**)&pC,   g_C);
    cudaGetSymbolAddress((void**)&pl,   g_l);
    cudaGetSymbolAddress((void**)&pIL,  g_IL);

    const int gemm_smem   = 4 * GSTG * 2 * 4;                  // 81920
    const int scores_smem = (2 * 128 * 68 + 256) * 4;          // 70656
    const int ctx_smem    = (2 * PSTG + 2 * VSTG + 128) * 4;   // 107008
    cudaFuncSetAttribute(gemm_v3<true>,  cudaFuncAttributeMaxDynamicSharedMemorySize, gemm_smem);
    cudaFuncSetAttribute(gemm_v3<false>, cudaFuncAttributeMaxDynamicSharedMemorySize, gemm_smem);
    cudaFuncSetAttribute(scores_v7,      cudaFuncAttributeMaxDynamicSharedMemorySize, scores_smem);
    cudaFuncSetAttribute(ctx_v7,         cudaFuncAttributeMaxDynamicSharedMemorySize, ctx_smem);

    // 1) prep
    concat_kernel<<<(DD * DD / 4) / 256, 256>>>(
        (const float4*)Wq, (const float4*)Wk, (const float4*)Wv, (const float4*)Wo,
        bq, bk, bv);
    roundx_kernel<<<((size_t)NR * DD / 4) / 256, 256>>>((const float4*)x);

    // 2) fused QKV projection (stores tf32-rounded outputs)
    gemm_v3<true><<<dim3(3072 / 128, NR / 128), 256, gemm_smem>>>(pX, pW3, pb3, pQKV, NR, 3072, DD);

    // 3) raw causal scores + per-tile row exp-sums
    scores_v7<<<dim3(SS / 128, SS / 128, BB * HH), 256, scores_smem>>>(pQKV, attn, pl);

    // 4) fold sums -> per-row 1/L
    reduce_stats<<<(32 * SS) / 256, 256>>>(pl, pIL);

    // 5) fused normalize + attn write + ctx = attn @ V
    ctx_v7<<<dim3(SS / 128, BB * HH), 256, ctx_smem>>>(attn, pQKV, pIL, pC);

    // 6) output projection (exact fp32 epilogue)
    gemm_v3<false><<<dim3(DD / 128, NR / 128), 256, gemm_smem>>>(pC, pWo, bo, out, NR, DD, DD);
}

// round 9
// speedup vs baseline: 1.7169x; 1.5603x over previous
#include <cuda_runtime.h>
#include <cuda_fp16.h>
#include <stdint.h>

#define BB 2
#define SS 2048
#define DD 1024
#define HH 16
#define NR (BB*SS)            // 4096 rows
#define ATT_SCALE 0.125f      // 1/sqrt(64)

// ---------------- device scratch (no cudaMalloc allowed) ----------------
static __device__ __half g_W3[3 * DD * DD];           // concat(Wq,Wk,Wv) fp16
static __device__ __half g_Wo[DD * DD];               // Wo fp16
static __device__ float  g_b3[3 * DD];
static __device__ __half g_X[(size_t)NR * DD];        // x fp16
static __device__ __half g_QKV[(size_t)NR * 3 * DD];  // (4096,3072) Q|K|V fp16
static __device__ __half g_VT[(size_t)32 * 64 * SS];  // V transposed: [z][d][s] fp16
static __device__ __half g_C[(size_t)NR * DD];        // ctx fp16

// ---------------- fp16 mma / cp.async helpers ----------------
__device__ __forceinline__ void mma16(float* c, const uint32_t* a, const uint32_t* b) {
    asm volatile(
        "mma.sync.aligned.m16n8k16.row.col.f32.f16.f16.f32 "
        "{%0,%1,%2,%3},{%4,%5,%6,%7},{%8,%9},{%0,%1,%2,%3};"
        : "+f"(c[0]), "+f"(c[1]), "+f"(c[2]), "+f"(c[3])
        : "r"(a[0]), "r"(a[1]), "r"(a[2]), "r"(a[3]), "r"(b[0]), "r"(b[1]));
}
__device__ __forceinline__ uint32_t pack_h2(float lo, float hi) {
    uint32_t r;
    asm("cvt.rn.f16x2.f32 %0, %1, %2;" : "=r"(r) : "f"(hi), "f"(lo));
    return r;
}
__device__ __forceinline__ void cp16(void* dst, const void* src) {
    uint32_t d = (uint32_t)__cvta_generic_to_shared(dst);
    asm volatile("cp.async.cg.shared.global [%0], [%1], 16;" :: "r"(d), "l"(src));
}
__device__ __forceinline__ void cp_commit() { asm volatile("cp.async.commit_group;"); }
template <int N>
__device__ __forceinline__ void cp_wait() { asm volatile("cp.async.wait_group %0;" :: "n"(N)); }

// ---------------- prep: concat weights -> fp16; x -> fp16 ----------------
__global__ void concat_h(const float4* __restrict__ Wq, const float4* __restrict__ Wk,
                         const float4* __restrict__ Wv, const float4* __restrict__ Wo4,
                         const float* __restrict__ bq, const float* __restrict__ bk,
                         const float* __restrict__ bv) {
    const int i = blockIdx.x * 256 + threadIdx.x;   // float4 index, < DD*DD/4
    float4 a = Wq[i], b = Wk[i], c = Wv[i], d = Wo4[i];
    __half2* w3 = (__half2*)g_W3;
    __half2* wo = (__half2*)g_Wo;
    const int q2 = DD * DD / 2;
    w3[2*i]              = __floats2half2_rn(a.x, a.y);
    w3[2*i + 1]          = __floats2half2_rn(a.z, a.w);
    w3[q2 + 2*i]         = __floats2half2_rn(b.x, b.y);
    w3[q2 + 2*i + 1]     = __floats2half2_rn(b.z, b.w);
    w3[2*q2 + 2*i]       = __floats2half2_rn(c.x, c.y);
    w3[2*q2 + 2*i + 1]   = __floats2half2_rn(c.z, c.w);
    wo[2*i]              = __floats2half2_rn(d.x, d.y);
    wo[2*i + 1]          = __floats2half2_rn(d.z, d.w);
    if (i < DD) {
        g_b3[i]          = bq[i];
        g_b3[DD + i]     = bk[i];
        g_b3[2 * DD + i] = bv[i];
    }
}
__global__ void roundx_h(const float4* __restrict__ x) {
    const size_t i = (size_t)blockIdx.x * 256 + threadIdx.x;
    float4 v = x[i];
    __half2* X = (__half2*)g_X;
    X[2*i]     = __floats2half2_rn(v.x, v.y);
    X[2*i + 1] = __floats2half2_rn(v.z, v.w);
}

// ---------------- NT GEMM fp16: C = A @ B^T + bias; 128x128, BK=32, 4-stage ----
#define HSTG (128*40)   // halves per operand stage (stride 40 halves)
template <bool OUT_HALF>
__global__ __launch_bounds__(256, 2) void gemm_h(
    const __half* __restrict__ A, const __half* __restrict__ Bw,
    const float* __restrict__ bias, void* __restrict__ Cv,
    int M, int N, int K)
{
    extern __shared__ char smraw[];
    __half* As = (__half*)smraw;          // [4][128][40]
    __half* Bs = As + 4 * HSTG;           // [4][128][40]

    const int t = threadIdx.x, lane = t & 31, w = t >> 5;
    const int g = lane >> 2, tg = lane & 3;
    const int wm = w & 3, wn = w >> 2;
    const int row0 = blockIdx.y * 128, col0 = blockIdx.x * 128;

    const int lrow = t >> 1, lseg = (t & 1) * 16;
    const __half* Ap = A  + (size_t)(row0 + lrow) * K + lseg;
    const __half* Bp = Bw + (size_t)(col0 + lrow) * K + lseg;
    __half* Asd = As + lrow * 40 + lseg;
    __half* Bsd = Bs + lrow * 40 + lseg;

    float acc[2][8][4];
#pragma unroll
    for (int i = 0; i < 2; i++)
#pragma unroll
        for (int j = 0; j < 8; j++)
#pragma unroll
            for (int q = 0; q < 4; q++) acc[i][j][q] = 0.f;

    const int nk = K / 32;
#pragma unroll
    for (int s = 0; s < 3; s++) {
        cp16(Asd + s * HSTG, Ap + s * 32);
        cp16(Asd + s * HSTG + 8, Ap + s * 32 + 8);
        cp16(Bsd + s * HSTG, Bp + s * 32);
        cp16(Bsd + s * HSTG + 8, Bp + s * 32 + 8);
        cp_commit();
    }

    for (int kc = 0; kc < nk; kc++) {
        cp_wait<2>();
        __syncthreads();
        if (kc + 3 < nk) {
            const int s = (kc + 3) & 3;
            const int k0 = (kc + 3) * 32;
            cp16(Asd + s * HSTG, Ap + k0);
            cp16(Asd + s * HSTG + 8, Ap + k0 + 8);
            cp16(Bsd + s * HSTG, Bp + k0);
            cp16(Bsd + s * HSTG + 8, Bp + k0 + 8);
        }
        cp_commit();

        const __half* a = As + (kc & 3) * HSTG;
        const __half* b = Bs + (kc & 3) * HSTG;
#pragma unroll
        for (int ks = 0; ks < 32; ks += 16) {
            uint32_t af[2][4], bf[8][2];
#pragma unroll
            for (int mt = 0; mt < 2; mt++) {
                const int r = wm * 32 + mt * 16 + g;
                af[mt][0] = *(const uint32_t*)(a + r * 40 + ks + 2 * tg);
                af[mt][1] = *(const uint32_t*)(a + (r + 8) * 40 + ks + 2 * tg);
                af[mt][2] = *(const uint32_t*)(a + r * 40 + ks + 8 + 2 * tg);
                af[mt][3] = *(const uint32_t*)(a + (r + 8) * 40 + ks + 8 + 2 * tg);
            }
#pragma unroll
            for (int nt = 0; nt < 8; nt++) {
                const int n = wn * 64 + nt * 8 + g;
                bf[nt][0] = *(const uint32_t*)(b + n * 40 + ks + 2 * tg);
                bf[nt][1] = *(const uint32_t*)(b + n * 40 + ks + 8 + 2 * tg);
            }
#pragma unroll
            for (int mt = 0; mt < 2; mt++)
#pragma unroll
                for (int nt = 0; nt < 8; nt++)
                    mma16(acc[mt][nt], af[mt], bf[nt]);
        }
    }

#pragma unroll
    for (int mt = 0; mt < 2; mt++) {
        const int r = row0 + wm * 32 + mt * 16 + g;
#pragma unroll
        for (int nt = 0; nt < 8; nt++) {
            const int cc = col0 + wn * 64 + nt * 8 + 2 * tg;
            const float b0 = bias[cc], b1 = bias[cc + 1];
            if (OUT_HALF) {
                __half* C = (__half*)Cv;
                *(__half2*)(C + (size_t)r * N + cc) =
                    __floats2half2_rn(acc[mt][nt][0] + b0, acc[mt][nt][1] + b1);
                *(__half2*)(C + (size_t)(r + 8) * N + cc) =
                    __floats2half2_rn(acc[mt][nt][2] + b0, acc[mt][nt][3] + b1);
            } else {
                float* C = (float*)Cv;
                float2 v0, v1;
                v0.x = acc[mt][nt][0] + b0; v0.y = acc[mt][nt][1] + b1;
                v1.x = acc[mt][nt][2] + b0; v1.y = acc[mt][nt][3] + b1;
                *(float2*)(C + (size_t)r * N + cc)       = v0;
                *(float2*)(C + (size_t)(r + 8) * N + cc) = v1;
            }
        }
    }
}

// ---------------- V transpose: g_QKV V-part -> g_VT[z][d][s] ----------------
__global__ void transpose_v(const __half* __restrict__ QKV, __half* __restrict__ VT)
{
    __shared__ __half ts[64 * 66];
    const int st = blockIdx.x, z = blockIdx.y;
    const int b = z >> 4, h = z & 15;
    const int t = threadIdx.x;
    for (int i = t; i < 4096; i += 256) {
        const int r = i >> 6, c = i & 63;   // r: token offset, c: dim
        ts[c * 66 + r] = QKV[((size_t)(b * SS) + st * 64 + r) * 3072 + 2 * DD + h * 64 + c];
    }
    __syncthreads();
    for (int i = t; i < 4096; i += 256) {
        const int d = i >> 6, s = i & 63;
        VT[((size_t)z * 64 + d) * SS + st * 64 + s] = ts[d * 66 + s];
    }
}

// ---------------- scores fp16: 128x128 tiles, 2-phase cp.async, K=64 ----------
__global__ __launch_bounds__(256, 2) void scores_h(
    const __half* __restrict__ QKV, float* __restrict__ attn)
{
    const int kt = blockIdx.x, qt = blockIdx.y, z = blockIdx.z;
    if (kt > qt) return;
    const int b = z >> 4, h = z & 15;

    extern __shared__ char smraw[];
    __half* Qs = (__half*)smraw;      // [128][72]
    __half* Ks = Qs + 128 * 72;       // [128][72]

    const int t = threadIdx.x, lane = t & 31, w = t >> 5;
    const int g = lane >> 2, tg = lane & 3;
    const int wm = w & 3, wn = w >> 2;

    const int lrow = t >> 1, off0 = (t & 1) * 16;
    const __half* Qp = QKV + ((size_t)(b * SS) + qt * 128 + lrow) * 3072 + h * 64;
    const __half* Kp = QKV + ((size_t)(b * SS) + kt * 128 + lrow) * 3072 + DD + h * 64;
    __half* Qsd = Qs + lrow * 72;
    __half* Ksd = Ks + lrow * 72;

    // phase 0: halves [0,32)
    cp16(Qsd + off0, Qp + off0);       cp16(Qsd + off0 + 8, Qp + off0 + 8);
    cp16(Ksd + off0, Kp + off0);       cp16(Ksd + off0 + 8, Kp + off0 + 8);
    cp_commit();
    // phase 1: halves [32,64)
    cp16(Qsd + 32 + off0, Qp + 32 + off0);  cp16(Qsd + 40 + off0, Qp + 40 + off0);
    cp16(Ksd + 32 + off0, Kp + 32 + off0);  cp16(Ksd + 40 + off0, Kp + 40 + off0);
    cp_commit();

    float acc[2][8][4];
#pragma unroll
    for (int i = 0; i < 2; i++)
#pragma unroll
        for (int j = 0; j < 8; j++)
#pragma unroll
            for (int q = 0; q < 4; q++) acc[i][j][q] = 0.f;

    cp_wait<1>();
    __syncthreads();

#pragma unroll
    for (int half_ = 0; half_ < 2; half_++) {
#pragma unroll
        for (int ks0 = 0; ks0 < 32; ks0 += 16) {
            const int ks = half_ * 32 + ks0;
            uint32_t af[2][4], bf[8][2];
#pragma unroll
            for (int mt = 0; mt < 2; mt++) {
                const int r = wm * 32 + mt * 16 + g;
                af[mt][0] = *(const uint32_t*)(Qs + r * 72 + ks + 2 * tg);
                af[mt][1] = *(const uint32_t*)(Qs + (r + 8) * 72 + ks + 2 * tg);
                af[mt][2] = *(const uint32_t*)(Qs + r * 72 + ks + 8 + 2 * tg);
                af[mt][3] = *(const uint32_t*)(Qs + (r + 8) * 72 + ks + 8 + 2 * tg);
            }
#pragma unroll
            for (int nt = 0; nt < 8; nt++) {
                const int n = wn * 64 + nt * 8 + g;
                bf[nt][0] = *(const uint32_t*)(Ks + n * 72 + ks + 2 * tg);
                bf[nt][1] = *(const uint32_t*)(Ks + n * 72 + ks + 8 + 2 * tg);
            }
#pragma unroll
            for (int mt = 0; mt < 2; mt++)
#pragma unroll
                for (int nt = 0; nt < 8; nt++)
                    mma16(acc[mt][nt], af[mt], bf[nt]);
        }
        if (half_ == 0) {
            cp_wait<0>();
            __syncthreads();
        }
    }

#pragma unroll
    for (int mt = 0; mt < 2; mt++) {
        const int r = qt * 128 + wm * 32 + mt * 16 + g;
#pragma unroll
        for (int nt = 0; nt < 8; nt++) {
            const int cc = kt * 128 + wn * 64 + nt * 8 + 2 * tg;
            float2 v0, v1;
            v0.x = acc[mt][nt][0] * ATT_SCALE; v0.y = acc[mt][nt][1] * ATT_SCALE;
            v1.x = acc[mt][nt][2] * ATT_SCALE; v1.y = acc[mt][nt][3] * ATT_SCALE;
            *(float2*)(attn + ((size_t)z * SS + r) * SS + cc)     = v0;
            *(float2*)(attn + ((size_t)z * SS + r + 8) * SS + cc) = v1;
        }
    }
}

// ---------------- softmax: causal-predicated loads, float4, zero-fills ----------
__global__ __launch_bounds__(256) void softmax_v8(float* __restrict__ attn)
{
    const size_t row = blockIdx.x;
    const int q = (int)(row & (SS - 1));
    float4* p = (float4*)(attn + row * (size_t)SS);
    const float* ps = (const float*)p;
    const int t = threadIdx.x;
    const int ia = 4 * t, ib = 1024 + 4 * t;
    const float NEG = -1e30f;

    float4 va = make_float4(NEG, NEG, NEG, NEG);
    float4 vb = make_float4(NEG, NEG, NEG, NEG);
    if (ia + 3 <= q) va = p[t];
    else if (ia <= q) {
        va.x = ps[ia];
        if (ia + 1 <= q) va.y = ps[ia + 1];
        if (ia + 2 <= q) va.z = ps[ia + 2];
    }
    if (ib + 3 <= q) vb = p[t + 256];
    else if (ib <= q) {
        vb.x = ps[ib];
        if (ib + 1 <= q) vb.y = ps[ib + 1];
        if (ib + 2 <= q) vb.z = ps[ib + 2];
    }

    float m = fmaxf(fmaxf(fmaxf(va.x, va.y), fmaxf(va.z, va.w)),
                    fmaxf(fmaxf(vb.x, vb.y), fmaxf(vb.z, vb.w)));
#pragma unroll
    for (int o = 16; o > 0; o >>= 1) m = fmaxf(m, __shfl_xor_sync(0xffffffffu, m, o));
    __shared__ float redm[8];
    __shared__ float reds[8];
    if ((t & 31) == 0) redm[t >> 5] = m;
    __syncthreads();
    float bm = redm[0];
#pragma unroll
    for (int w = 1; w < 8; w++) bm = fmaxf(bm, redm[w]);

    // masked lanes hold -1e30 -> exp underflows to exactly 0
    va.x = __expf(va.x - bm); va.y = __expf(va.y - bm);
    va.z = __expf(va.z - bm); va.w = __expf(va.w - bm);
    vb.x = __expf(vb.x - bm); vb.y = __expf(vb.y - bm);
    vb.z = __expf(vb.z - bm); vb.w = __expf(vb.w - bm);

    float s = va.x + va.y + va.z + va.w + vb.x + vb.y + vb.z + vb.w;
#pragma unroll
    for (int o = 16; o > 0; o >>= 1) s += __shfl_xor_sync(0xffffffffu, s, o);
    if ((t & 31) == 0) reds[t >> 5] = s;
    __syncthreads();
    float tot = 0.f;
#pragma unroll
    for (int w = 0; w < 8; w++) tot += reds[w];
    const float inv = 1.0f / tot;

    va.x *= inv; va.y *= inv; va.z *= inv; va.w *= inv;
    vb.x *= inv; vb.y *= inv; vb.z *= inv; vb.w *= inv;
    p[t] = va;
    p[t + 256] = vb;
}

// ---------------- ctx fp16: P fp32->h2 in-register, V from VT, 2-stage ----------
#define PST (128*72)    // f32 per P stage
#define VST (64*72)     // halves per V stage
__global__ __launch_bounds__(256, 2) void ctx_h(
    const float* __restrict__ attn, const __half* __restrict__ VT,
    __half* __restrict__ Cout)
{
    extern __shared__ char smraw[];
    float* Ps  = (float*)smraw;                 // [2][128][72] fp32
    __half* Vs = (__half*)(Ps + 2 * PST);       // [2][64][72]  fp16

    const int qt = 15 - blockIdx.x;             // longest first
    const int z = blockIdx.y;
    const int b = z >> 4, h = z & 15;
    const int t = threadIdx.x, lane = t & 31, w = t >> 5;
    const int g = lane >> 2, tg = lane & 3;
    const int wm = w & 3, wn = w >> 2;

    const int prow = t >> 1, pseg = (t & 1) * 32;
    const int vrow = t >> 2, vseg = (t & 3) * 16;
    const float* Pp = attn + ((size_t)z * SS + qt * 128 + prow) * SS + pseg;
    const __half* Vp = VT + ((size_t)z * 64 + vrow) * SS + vseg;
    float*  Psd = Ps + prow * 72 + pseg;
    __half* Vsd = Vs + vrow * 72 + vseg;

    const int cnt = 2 * qt + 2;

    float acc[2][4][4];
#pragma unroll
    for (int i = 0; i < 2; i++)
#pragma unroll
        for (int j = 0; j < 4; j++)
#pragma unroll
            for (int q = 0; q < 4; q++) acc[i][j][q] = 0.f;

    // prologue: stage 0 = chunk 0
#pragma unroll
    for (int j = 0; j < 8; j++) cp16(Psd + j * 4, Pp + j * 4);
    cp16(Vsd, Vp); cp16(Vsd + 8, Vp + 8);
    cp_commit();

    for (int kti = 0; kti < cnt; kti++) {
        if (kti + 1 < cnt) {
            const int st = (kti + 1) & 1;
#pragma unroll
            for (int j = 0; j < 8; j++)
                cp16(Psd + st * PST + j * 4, Pp + (kti + 1) * 64 + j * 4);
            cp16(Vsd + st * VST, Vp + (kti + 1) * 64);
            cp16(Vsd + st * VST + 8, Vp + (kti + 1) * 64 + 8);
        }
        cp_commit();
        cp_wait<1>();
        __syncthreads();

        const float*  pp = Ps + (kti & 1) * PST;
        const __half* vv = Vs + (kti & 1) * VST;
#pragma unroll
        for (int ks = 0; ks < 64; ks += 16) {
            uint32_t af[2][4], bf[4][2];
#pragma unroll
            for (int mt = 0; mt < 2; mt++) {
                const int r = wm * 32 + mt * 16 + g;
                float2 q0 = *(const float2*)(pp + r * 72 + ks + 2 * tg);
                float2 q1 = *(const float2*)(pp + (r + 8) * 72 + ks + 2 * tg);
                float2 q2 = *(const float2*)(pp + r * 72 + ks + 8 + 2 * tg);
                float2 q3 = *(const float2*)(pp + (r + 8) * 72 + ks + 8 + 2 * tg);
                af[mt][0] = pack_h2(q0.x, q0.y);
                af[mt][1] = pack_h2(q1.x, q1.y);
                af[mt][2] = pack_h2(q2.x, q2.y);
                af[mt][3] = pack_h2(q3.x, q3.y);
            }
#pragma unroll
            for (int nt = 0; nt < 4; nt++) {
                const int n = wn * 32 + nt * 8 + g;
                bf[nt][0] = *(const uint32_t*)(vv + n * 72 + ks + 2 * tg);
                bf[nt][1] = *(const uint32_t*)(vv + n * 72 + ks + 8 + 2 * tg);
            }
#pragma unroll
            for (int mt = 0; mt < 2; mt++)
#pragma unroll
                for (int nt = 0; nt < 4; nt++)
                    mma16(acc[mt][nt], af[mt], bf[nt]);
        }
        __syncthreads();
    }

#pragma unroll
    for (int mt = 0; mt < 2; mt++) {
        const int qrow = qt * 128 + wm * 32 + mt * 16 + g;
#pragma unroll
        for (int nt = 0; nt < 4; nt++) {
            const int cc = h * 64 + wn * 32 + nt * 8 + 2 * tg;
            *(__half2*)(Cout + ((size_t)(b * SS) + qrow) * DD + cc) =
                __floats2half2_rn(acc[mt][nt][0], acc[mt][nt][1]);
            *(__half2*)(Cout + ((size_t)(b * SS) + qrow + 8) * DD + cc) =
                __floats2half2_rn(acc[mt][nt][2], acc[mt][nt][3]);
        }
    }
}

// ---------------- launch ----------------
extern "C" void kernel_launch(void* const* d_in, const int* in_sizes, int n_in,
                              void* d_out, int out_size)
{
    const float* x  = (const float*)d_in[0];
    const float* Wq = (const float*)d_in[1];
    const float* bq = (const float*)d_in[2];
    const float* Wk = (const float*)d_in[3];
    const float* bk = (const float*)d_in[4];
    const float* Wv = (const float*)d_in[5];
    const float* bv = (const float*)d_in[6];
    const float* Wo = (const float*)d_in[7];
    const float* bo = (const float*)d_in[8];

    float* out  = (float*)d_out;
    float* attn = out + (size_t)NR * DD;   // tuple order: (out, attn)

    __half *pW3, *pWo, *pX, *pQKV, *pVT, *pC;
    float *pb3;
    cudaGetSymbolAddress((void**)&pW3,  g_W3);
    cudaGetSymbolAddress((void**)&pWo,  g_Wo);
    cudaGetSymbolAddress((void**)&pb3,  g_b3);
    cudaGetSymbolAddress((void**)&pX,   g_X);
    cudaGetSymbolAddress((void**)&pQKV, g_QKV);
    cudaGetSymbolAddress((void**)&pVT,  g_VT);
    cudaGetSymbolAddress((void**)&pC,   g_C);

    const int gemm_smem   = 4 * HSTG * 2 * 2;              // 81920 B
    const int scores_smem = 2 * 128 * 72 * 2;              // 36864 B
    const int ctx_smem    = 2 * PST * 4 + 2 * VST * 2;     // 92160 B
    cudaFuncSetAttribute(gemm_h<true>,  cudaFuncAttributeMaxDynamicSharedMemorySize, gemm_smem);
    cudaFuncSetAttribute(gemm_h<false>, cudaFuncAttributeMaxDynamicSharedMemorySize, gemm_smem);
    cudaFuncSetAttribute(scores_h,      cudaFuncAttributeMaxDynamicSharedMemorySize, scores_smem);
    cudaFuncSetAttribute(ctx_h,         cudaFuncAttributeMaxDynamicSharedMemorySize, ctx_smem);

    // 1) prep
    concat_h<<<(DD * DD / 4) / 256, 256>>>(
        (const float4*)Wq, (const float4*)Wk, (const float4*)Wv, (const float4*)Wo,
        bq, bk, bv);
    roundx_h<<<((size_t)NR * DD / 4) / 256, 256>>>((const float4*)x);

    // 2) fused QKV projection -> fp16
    gemm_h<true><<<dim3(3072 / 128, NR / 128), 256, gemm_smem>>>(pX, pW3, pb3, pQKV, NR, 3072, DD);

    // 3) transpose V slice for ctx B-operand layout
    transpose_v<<<dim3(SS / 64, BB * HH), 256>>>(pQKV, pVT);

    // 4) raw causal scores (fp16 mma) -> attn region fp32
    scores_h<<<dim3(SS / 128, SS / 128, BB * HH), 256, scores_smem>>>(pQKV, attn);

    // 5) softmax per row (causal-predicated loads; zero-fills masked region)
    softmax_v8<<<BB * HH * SS, 256>>>(attn);

    // 6) ctx = attn @ V (fp16 mma) -> fp16 ctx
    ctx_h<<<dim3(SS / 128, BB * HH), 256, ctx_smem>>>(attn, pVT, pC);

    // 7) output projection (fp32 out)
    gemm_h<false><<<dim3(DD / 128, NR / 128), 256, gemm_smem>>>(pC, pWo, bo, out, NR, DD, DD);
}

// round 10
// speedup vs baseline: 1.8216x; 1.0610x over previous
#include <cuda_runtime.h>
#include <cuda_fp16.h>
#include <stdint.h>

#define BB 2
#define SS 2048
#define DD 1024
#define HH 16
#define NR (BB*SS)            // 4096 rows
#define ATT_SCALE 0.125f      // 1/sqrt(64)

// ---------------- device scratch (no cudaMalloc allowed) ----------------
static __device__ __half g_W3[3 * DD * DD];           // concat(Wq,Wk,Wv) fp16
static __device__ __half g_Wo[DD * DD];               // Wo fp16
static __device__ float  g_b3[3 * DD];
static __device__ __half g_X[(size_t)NR * DD];        // x fp16
static __device__ __half g_QKV[(size_t)NR * 3 * DD];  // (4096,3072) Q|K|V fp16
static __device__ __half g_VT[(size_t)32 * 64 * SS];  // V transposed: [z][d][s] fp16
static __device__ __half g_C[(size_t)NR * DD];        // ctx fp16

// ---------------- fp16 mma / ldmatrix / cp.async helpers ----------------
__device__ __forceinline__ void mma16(float* c, const uint32_t* a, const uint32_t* b) {
    asm volatile(
        "mma.sync.aligned.m16n8k16.row.col.f32.f16.f16.f32 "
        "{%0,%1,%2,%3},{%4,%5,%6,%7},{%8,%9},{%0,%1,%2,%3};"
        : "+f"(c[0]), "+f"(c[1]), "+f"(c[2]), "+f"(c[3])
        : "r"(a[0]), "r"(a[1]), "r"(a[2]), "r"(a[3]), "r"(b[0]), "r"(b[1]));
}
__device__ __forceinline__ void ldsm4(uint32_t& r0, uint32_t& r1, uint32_t& r2,
                                      uint32_t& r3, uint32_t addr) {
    asm volatile("ldmatrix.sync.aligned.m8n8.x4.shared.b16 {%0,%1,%2,%3}, [%4];"
                 : "=r"(r0), "=r"(r1), "=r"(r2), "=r"(r3) : "r"(addr));
}
__device__ __forceinline__ uint32_t pack_h2(float lo, float hi) {
    uint32_t r;
    asm("cvt.rn.f16x2.f32 %0, %1, %2;" : "=r"(r) : "f"(hi), "f"(lo));
    return r;
}
__device__ __forceinline__ void cp16(void* dst, const void* src) {
    uint32_t d = (uint32_t)__cvta_generic_to_shared(dst);
    asm volatile("cp.async.cg.shared.global [%0], [%1], 16;" :: "r"(d), "l"(src));
}
__device__ __forceinline__ void cp_commit() { asm volatile("cp.async.commit_group;"); }
template <int N>
__device__ __forceinline__ void cp_wait() { asm volatile("cp.async.wait_group %0;" :: "n"(N)); }

// ---------------- prep: concat weights -> fp16; x -> fp16 ----------------
__global__ void concat_h(const float4* __restrict__ Wq, const float4* __restrict__ Wk,
                         const float4* __restrict__ Wv, const float4* __restrict__ Wo4,
                         const float* __restrict__ bq, const float* __restrict__ bk,
                         const float* __restrict__ bv) {
    const int i = blockIdx.x * 256 + threadIdx.x;   // float4 index, < DD*DD/4
    float4 a = Wq[i], b = Wk[i], c = Wv[i], d = Wo4[i];
    __half2* w3 = (__half2*)g_W3;
    __half2* wo = (__half2*)g_Wo;
    const int q2 = DD * DD / 2;
    w3[2*i]              = __floats2half2_rn(a.x, a.y);
    w3[2*i + 1]          = __floats2half2_rn(a.z, a.w);
    w3[q2 + 2*i]         = __floats2half2_rn(b.x, b.y);
    w3[q2 + 2*i + 1]     = __floats2half2_rn(b.z, b.w);
    w3[2*q2 + 2*i]       = __floats2half2_rn(c.x, c.y);
    w3[2*q2 + 2*i + 1]   = __floats2half2_rn(c.z, c.w);
    wo[2*i]              = __floats2half2_rn(d.x, d.y);
    wo[2*i + 1]          = __floats2half2_rn(d.z, d.w);
    if (i < DD) {
        g_b3[i]          = bq[i];
        g_b3[DD + i]     = bk[i];
        g_b3[2 * DD + i] = bv[i];
    }
}
__global__ void roundx_h(const float4* __restrict__ x) {
    const size_t i = (size_t)blockIdx.x * 256 + threadIdx.x;
    float4 v = x[i];
    __half2* X = (__half2*)g_X;
    X[2*i]     = __floats2half2_rn(v.x, v.y);
    X[2*i + 1] = __floats2half2_rn(v.z, v.w);
}

// ---------------- NT GEMM fp16: C = A @ B^T + bias; 128x128, BK=32, 4-stage ----
#define HSTG (128*40)   // halves per operand stage (stride 40 halves)
template <bool OUT_HALF>
__global__ __launch_bounds__(256, 2) void gemm_h(
    const __half* __restrict__ A, const __half* __restrict__ Bw,
    const float* __restrict__ bias, void* __restrict__ Cv,
    int M, int N, int K)
{
    extern __shared__ char smraw[];
    __half* As = (__half*)smraw;          // [4][128][40]
    __half* Bs = As + 4 * HSTG;           // [4][128][40]
    const uint32_t smem_u = (uint32_t)__cvta_generic_to_shared(smraw);
    const uint32_t bs_u   = smem_u + 4 * HSTG * 2;

    const int t = threadIdx.x, lane = t & 31, w = t >> 5;
    const int g = lane >> 2, tg = lane & 3;
    const int wm = w & 3, wn = w >> 2;
    const int row0 = blockIdx.y * 128, col0 = blockIdx.x * 128;

    // ldmatrix per-lane byte offsets
    const int li = lane >> 3, lj = lane & 7;
    uint32_t aoff[2], boff[4];
#pragma unroll
    for (int mt = 0; mt < 2; mt++)
        aoff[mt] = (uint32_t)(((wm * 32 + mt * 16 + (li & 1) * 8 + lj) * 40 + (li >> 1) * 8) * 2);
#pragma unroll
    for (int p = 0; p < 4; p++)
        boff[p] = (uint32_t)(((wn * 64 + p * 16 + (li >> 1) * 8 + lj) * 40 + (li & 1) * 8) * 2);

    const int lrow = t >> 1, lseg = (t & 1) * 16;
    const __half* Ap = A  + (size_t)(row0 + lrow) * K + lseg;
    const __half* Bp = Bw + (size_t)(col0 + lrow) * K + lseg;
    __half* Asd = As + lrow * 40 + lseg;
    __half* Bsd = Bs + lrow * 40 + lseg;

    float acc[2][8][4];
#pragma unroll
    for (int i = 0; i < 2; i++)
#pragma unroll
        for (int j = 0; j < 8; j++)
#pragma unroll
            for (int q = 0; q < 4; q++) acc[i][j][q] = 0.f;

    const int nk = K / 32;
#pragma unroll
    for (int s = 0; s < 3; s++) {
        cp16(Asd + s * HSTG, Ap + s * 32);
        cp16(Asd + s * HSTG + 8, Ap + s * 32 + 8);
        cp16(Bsd + s * HSTG, Bp + s * 32);
        cp16(Bsd + s * HSTG + 8, Bp + s * 32 + 8);
        cp_commit();
    }

    for (int kc = 0; kc < nk; kc++) {
        cp_wait<2>();
        __syncthreads();
        if (kc + 3 < nk) {
            const int s = (kc + 3) & 3;
            const int k0 = (kc + 3) * 32;
            cp16(Asd + s * HSTG, Ap + k0);
            cp16(Asd + s * HSTG + 8, Ap + k0 + 8);
            cp16(Bsd + s * HSTG, Bp + k0);
            cp16(Bsd + s * HSTG + 8, Bp + k0 + 8);
        }
        cp_commit();

        const uint32_t a_stage = smem_u + (uint32_t)((kc & 3) * HSTG * 2);
        const uint32_t b_stage = bs_u   + (uint32_t)((kc & 3) * HSTG * 2);
#pragma unroll
        for (int ks = 0; ks < 32; ks += 16) {
            uint32_t af[2][4], bf[8][2];
            ldsm4(af[0][0], af[0][1], af[0][2], af[0][3], a_stage + ks * 2 + aoff[0]);
            ldsm4(af[1][0], af[1][1], af[1][2], af[1][3], a_stage + ks * 2 + aoff[1]);
#pragma unroll
            for (int p = 0; p < 4; p++)
                ldsm4(bf[2*p][0], bf[2*p][1], bf[2*p+1][0], bf[2*p+1][1],
                      b_stage + ks * 2 + boff[p]);
#pragma unroll
            for (int mt = 0; mt < 2; mt++)
#pragma unroll
                for (int nt = 0; nt < 8; nt++)
                    mma16(acc[mt][nt], af[mt], bf[nt]);
        }
    }

#pragma unroll
    for (int mt = 0; mt < 2; mt++) {
        const int r = row0 + wm * 32 + mt * 16 + g;
#pragma unroll
        for (int nt = 0; nt < 8; nt++) {
            const int cc = col0 + wn * 64 + nt * 8 + 2 * tg;
            const float b0 = bias[cc], b1 = bias[cc + 1];
            if (OUT_HALF) {
                __half* C = (__half*)Cv;
                *(__half2*)(C + (size_t)r * N + cc) =
                    __floats2half2_rn(acc[mt][nt][0] + b0, acc[mt][nt][1] + b1);
                *(__half2*)(C + (size_t)(r + 8) * N + cc) =
                    __floats2half2_rn(acc[mt][nt][2] + b0, acc[mt][nt][3] + b1);
            } else {
                float* C = (float*)Cv;
                float2 v0, v1;
                v0.x = acc[mt][nt][0] + b0; v0.y = acc[mt][nt][1] + b1;
                v1.x = acc[mt][nt][2] + b0; v1.y = acc[mt][nt][3] + b1;
                *(float2*)(C + (size_t)r * N + cc)       = v0;
                *(float2*)(C + (size_t)(r + 8) * N + cc) = v1;
            }
        }
    }
}

// ---------------- V transpose: g_QKV V-part -> g_VT[z][d][s] ----------------
__global__ void transpose_v(const __half* __restrict__ QKV, __half* __restrict__ VT)
{
    __shared__ __half ts[64 * 66];
    const int st = blockIdx.x, z = blockIdx.y;
    const int b = z >> 4, h = z & 15;
    const int t = threadIdx.x;
    for (int i = t; i < 4096; i += 256) {
        const int r = i >> 6, c = i & 63;   // r: token offset, c: dim
        ts[c * 66 + r] = QKV[((size_t)(b * SS) + st * 64 + r) * 3072 + 2 * DD + h * 64 + c];
    }
    __syncthreads();
    for (int i = t; i < 4096; i += 256) {
        const int d = i >> 6, s = i & 63;
        VT[((size_t)z * 64 + d) * SS + st * 64 + s] = ts[d * 66 + s];
    }
}

// ---------------- scores fp16: 128x128 tiles, 2-phase cp.async, K=64 ----------
__global__ __launch_bounds__(256, 2) void scores_h(
    const __half* __restrict__ QKV, float* __restrict__ attn)
{
    const int kt = blockIdx.x, qt = blockIdx.y, z = blockIdx.z;
    if (kt > qt) return;
    const int b = z >> 4, h = z & 15;

    extern __shared__ char smraw[];
    __half* Qs = (__half*)smraw;      // [128][72]
    __half* Ks = Qs + 128 * 72;       // [128][72]
    const uint32_t smem_u = (uint32_t)__cvta_generic_to_shared(smraw);
    const uint32_t ks_u   = smem_u + 128 * 72 * 2;

    const int t = threadIdx.x, lane = t & 31, w = t >> 5;
    const int g = lane >> 2, tg = lane & 3;
    const int wm = w & 3, wn = w >> 2;

    const int li = lane >> 3, lj = lane & 7;
    uint32_t aoff[2], boff[4];
#pragma unroll
    for (int mt = 0; mt < 2; mt++)
        aoff[mt] = (uint32_t)(((wm * 32 + mt * 16 + (li & 1) * 8 + lj) * 72 + (li >> 1) * 8) * 2);
#pragma unroll
    for (int p = 0; p < 4; p++)
        boff[p] = (uint32_t)(((wn * 64 + p * 16 + (li >> 1) * 8 + lj) * 72 + (li & 1) * 8) * 2);

    const int lrow = t >> 1, off0 = (t & 1) * 16;
    const __half* Qp = QKV + ((size_t)(b * SS) + qt * 128 + lrow) * 3072 + h * 64;
    const __half* Kp = QKV + ((size_t)(b * SS) + kt * 128 + lrow) * 3072 + DD + h * 64;
    __half* Qsd = Qs + lrow * 72;
    __half* Ksd = Ks + lrow * 72;

    // phase 0: halves [0,32)
    cp16(Qsd + off0, Qp + off0);       cp16(Qsd + off0 + 8, Qp + off0 + 8);
    cp16(Ksd + off0, Kp + off0);       cp16(Ksd + off0 + 8, Kp + off0 + 8);
    cp_commit();
    // phase 1: halves [32,64)
    cp16(Qsd + 32 + off0, Qp + 32 + off0);  cp16(Qsd + 40 + off0, Qp + 40 + off0);
    cp16(Ksd + 32 + off0, Kp + 32 + off0);  cp16(Ksd + 40 + off0, Kp + 40 + off0);
    cp_commit();

    float acc[2][8][4];
#pragma unroll
    for (int i = 0; i < 2; i++)
#pragma unroll
        for (int j = 0; j < 8; j++)
#pragma unroll
            for (int q = 0; q < 4; q++) acc[i][j][q] = 0.f;

    cp_wait<1>();
    __syncthreads();

#pragma unroll
    for (int half_ = 0; half_ < 2; half_++) {
#pragma unroll
        for (int ks0 = 0; ks0 < 32; ks0 += 16) {
            const int ks = half_ * 32 + ks0;
            uint32_t af[2][4], bf[8][2];
            ldsm4(af[0][0], af[0][1], af[0][2], af[0][3], smem_u + ks * 2 + aoff[0]);
            ldsm4(af[1][0], af[1][1], af[1][2], af[1][3], smem_u + ks * 2 + aoff[1]);
#pragma unroll
            for (int p = 0; p < 4; p++)
                ldsm4(bf[2*p][0], bf[2*p][1], bf[2*p+1][0], bf[2*p+1][1],
                      ks_u + ks * 2 + boff[p]);
#pragma unroll
            for (int mt = 0; mt < 2; mt++)
#pragma unroll
                for (int nt = 0; nt < 8; nt++)
                    mma16(acc[mt][nt], af[mt], bf[nt]);
        }
        if (half_ == 0) {
            cp_wait<0>();
            __syncthreads();
        }
    }

#pragma unroll
    for (int mt = 0; mt < 2; mt++) {
        const int r = qt * 128 + wm * 32 + mt * 16 + g;
#pragma unroll
        for (int nt = 0; nt < 8; nt++) {
            const int cc = kt * 128 + wn * 64 + nt * 8 + 2 * tg;
            float2 v0, v1;
            v0.x = acc[mt][nt][0] * ATT_SCALE; v0.y = acc[mt][nt][1] * ATT_SCALE;
            v1.x = acc[mt][nt][2] * ATT_SCALE; v1.y = acc[mt][nt][3] * ATT_SCALE;
            *(float2*)(attn + ((size_t)z * SS + r) * SS + cc)     = v0;
            *(float2*)(attn + ((size_t)z * SS + r + 8) * SS + cc) = v1;
        }
    }
}

// ---------------- softmax: causal-predicated loads, float4, zero-fills ----------
__global__ __launch_bounds__(256) void softmax_v8(float* __restrict__ attn)
{
    const size_t row = blockIdx.x;
    const int q = (int)(row & (SS - 1));
    float4* p = (float4*)(attn + row * (size_t)SS);
    const float* ps = (const float*)p;
    const int t = threadIdx.x;
    const int ia = 4 * t, ib = 1024 + 4 * t;
    const float NEG = -1e30f;

    float4 va = make_float4(NEG, NEG, NEG, NEG);
    float4 vb = make_float4(NEG, NEG, NEG, NEG);
    if (ia + 3 <= q) va = p[t];
    else if (ia <= q) {
        va.x = ps[ia];
        if (ia + 1 <= q) va.y = ps[ia + 1];
        if (ia + 2 <= q) va.z = ps[ia + 2];
    }
    if (ib + 3 <= q) vb = p[t + 256];
    else if (ib <= q) {
        vb.x = ps[ib];
        if (ib + 1 <= q) vb.y = ps[ib + 1];
        if (ib + 2 <= q) vb.z = ps[ib + 2];
    }

    float m = fmaxf(fmaxf(fmaxf(va.x, va.y), fmaxf(va.z, va.w)),
                    fmaxf(fmaxf(vb.x, vb.y), fmaxf(vb.z, vb.w)));
#pragma unroll
    for (int o = 16; o > 0; o >>= 1) m = fmaxf(m, __shfl_xor_sync(0xffffffffu, m, o));
    __shared__ float redm[8];
    __shared__ float reds[8];
    if ((t & 31) == 0) redm[t >> 5] = m;
    __syncthreads();
    float bm = redm[0];
#pragma unroll
    for (int w = 1; w < 8; w++) bm = fmaxf(bm, redm[w]);

    va.x = __expf(va.x - bm); va.y = __expf(va.y - bm);
    va.z = __expf(va.z - bm); va.w = __expf(va.w - bm);
    vb.x = __expf(vb.x - bm); vb.y = __expf(vb.y - bm);
    vb.z = __expf(vb.z - bm); vb.w = __expf(vb.w - bm);

    float s = va.x + va.y + va.z + va.w + vb.x + vb.y + vb.z + vb.w;
#pragma unroll
    for (int o = 16; o > 0; o >>= 1) s += __shfl_xor_sync(0xffffffffu, s, o);
    if ((t & 31) == 0) reds[t >> 5] = s;
    __syncthreads();
    float tot = 0.f;
#pragma unroll
    for (int w = 0; w < 8; w++) tot += reds[w];
    const float inv = 1.0f / tot;

    va.x *= inv; va.y *= inv; va.z *= inv; va.w *= inv;
    vb.x *= inv; vb.y *= inv; vb.z *= inv; vb.w *= inv;
    p[t] = va;
    p[t + 256] = vb;
}

// ---------------- ctx fp16: P fp32->h2 in-register, V from VT, 2-stage ----------
#define PST (128*72)    // f32 per P stage
#define VST (64*72)     // halves per V stage
__global__ __launch_bounds__(256, 2) void ctx_h(
    const float* __restrict__ attn, const __half* __restrict__ VT,
    __half* __restrict__ Cout)
{
    extern __shared__ char smraw[];
    float* Ps  = (float*)smraw;                 // [2][128][72] fp32
    __half* Vs = (__half*)(Ps + 2 * PST);       // [2][64][72]  fp16
    const uint32_t smem_u = (uint32_t)__cvta_generic_to_shared(smraw);
    const uint32_t vs_u   = smem_u + 2 * PST * 4;

    const int qt = 15 - blockIdx.x;             // longest first
    const int z = blockIdx.y;
    const int b = z >> 4, h = z & 15;
    const int t = threadIdx.x, lane = t & 31, w = t >> 5;
    const int g = lane >> 2, tg = lane & 3;
    const int wm = w & 3, wn = w >> 2;

    const int li = lane >> 3, lj = lane & 7;
    uint32_t boff[2];
#pragma unroll
    for (int p = 0; p < 2; p++)
        boff[p] = (uint32_t)(((wn * 32 + p * 16 + (li >> 1) * 8 + lj) * 72 + (li & 1) * 8) * 2);

    const int prow = t >> 1, pseg = (t & 1) * 32;
    const int vrow = t >> 2, vseg = (t & 3) * 16;
    const float* Pp = attn + ((size_t)z * SS + qt * 128 + prow) * SS + pseg;
    const __half* Vp = VT + ((size_t)z * 64 + vrow) * SS + vseg;
    float*  Psd = Ps + prow * 72 + pseg;
    __half* Vsd = Vs + vrow * 72 + vseg;

    const int cnt = 2 * qt + 2;

    float acc[2][4][4];
#pragma unroll
    for (int i = 0; i < 2; i++)
#pragma unroll
        for (int j = 0; j < 4; j++)
#pragma unroll
            for (int q = 0; q < 4; q++) acc[i][j][q] = 0.f;

    // prologue: stage 0 = chunk 0
#pragma unroll
    for (int j = 0; j < 8; j++) cp16(Psd + j * 4, Pp + j * 4);
    cp16(Vsd, Vp); cp16(Vsd + 8, Vp + 8);
    cp_commit();

    for (int kti = 0; kti < cnt; kti++) {
        if (kti + 1 < cnt) {
            const int st = (kti + 1) & 1;
#pragma unroll
            for (int j = 0; j < 8; j++)
                cp16(Psd + st * PST + j * 4, Pp + (kti + 1) * 64 + j * 4);
            cp16(Vsd + st * VST, Vp + (kti + 1) * 64);
            cp16(Vsd + st * VST + 8, Vp + (kti + 1) * 64 + 8);
        }
        cp_commit();
        cp_wait<1>();
        __syncthreads();

        const float* pp = Ps + (kti & 1) * PST;
        const uint32_t vstage = vs_u + (uint32_t)((kti & 1) * VST * 2);
#pragma unroll
        for (int ks = 0; ks < 64; ks += 16) {
            uint32_t af[2][4], bf[4][2];
#pragma unroll
            for (int mt = 0; mt < 2; mt++) {
                const int r = wm * 32 + mt * 16 + g;
                float2 q0 = *(const float2*)(pp + r * 72 + ks + 2 * tg);
                float2 q1 = *(const float2*)(pp + (r + 8) * 72 + ks + 2 * tg);
                float2 q2 = *(const float2*)(pp + r * 72 + ks + 8 + 2 * tg);
                float2 q3 = *(const float2*)(pp + (r + 8) * 72 + ks + 8 + 2 * tg);
                af[mt][0] = pack_h2(q0.x, q0.y);
                af[mt][1] = pack_h2(q1.x, q1.y);
                af[mt][2] = pack_h2(q2.x, q2.y);
                af[mt][3] = pack_h2(q3.x, q3.y);
            }
            ldsm4(bf[0][0], bf[0][1], bf[1][0], bf[1][1], vstage + ks * 2 + boff[0]);
            ldsm4(bf[2][0], bf[2][1], bf[3][0], bf[3][1], vstage + ks * 2 + boff[1]);
#pragma unroll
            for (int mt = 0; mt < 2; mt++)
#pragma unroll
                for (int nt = 0; nt < 4; nt++)
                    mma16(acc[mt][nt], af[mt], bf[nt]);
        }
        __syncthreads();
    }

#pragma unroll
    for (int mt = 0; mt < 2; mt++) {
        const int qrow = qt * 128 + wm * 32 + mt * 16 + g;
#pragma unroll
        for (int nt = 0; nt < 4; nt++) {
            const int cc = h * 64 + wn * 32 + nt * 8 + 2 * tg;
            *(__half2*)(Cout + ((size_t)(b * SS) + qrow) * DD + cc) =
                __floats2half2_rn(acc[mt][nt][0], acc[mt][nt][1]);
            *(__half2*)(Cout + ((size_t)(b * SS) + qrow + 8) * DD + cc) =
                __floats2half2_rn(acc[mt][nt][2], acc[mt][nt][3]);
        }
    }
}

// ---------------- launch ----------------
extern "C" void kernel_launch(void* const* d_in, const int* in_sizes, int n_in,
                              void* d_out, int out_size)
{
    const float* x  = (const float*)d_in[0];
    const float* Wq = (const float*)d_in[1];
    const float* bq = (const float*)d_in[2];
    const float* Wk = (const float*)d_in[3];
    const float* bk = (const float*)d_in[4];
    const float* Wv = (const float*)d_in[5];
    const float* bv = (const float*)d_in[6];
    const float* Wo = (const float*)d_in[7];
    const float* bo = (const float*)d_in[8];

    float* out  = (float*)d_out;
    float* attn = out + (size_t)NR * DD;   // tuple order: (out, attn)

    __half *pW3, *pWo, *pX, *pQKV, *pVT, *pC;
    float *pb3;
    cudaGetSymbolAddress((void**)&pW3,  g_W3);
    cudaGetSymbolAddress((void**)&pWo,  g_Wo);
    cudaGetSymbolAddress((void**)&pb3,  g_b3);
    cudaGetSymbolAddress((void**)&pX,   g_X);
    cudaGetSymbolAddress((void**)&pQKV, g_QKV);
    cudaGetSymbolAddress((void**)&pVT,  g_VT);
    cudaGetSymbolAddress((void**)&pC,   g_C);

    const int gemm_smem   = 4 * HSTG * 2 * 2;              // 81920 B
    const int scores_smem = 2 * 128 * 72 * 2;              // 36864 B
    const int ctx_smem    = 2 * PST * 4 + 2 * VST * 2;     // 92160 B
    cudaFuncSetAttribute(gemm_h<true>,  cudaFuncAttributeMaxDynamicSharedMemorySize, gemm_smem);
    cudaFuncSetAttribute(gemm_h<false>, cudaFuncAttributeMaxDynamicSharedMemorySize, gemm_smem);
    cudaFuncSetAttribute(scores_h,      cudaFuncAttributeMaxDynamicSharedMemorySize, scores_smem);
    cudaFuncSetAttribute(ctx_h,         cudaFuncAttributeMaxDynamicSharedMemorySize, ctx_smem);

    // 1) prep
    concat_h<<<(DD * DD / 4) / 256, 256>>>(
        (const float4*)Wq, (const float4*)Wk, (const float4*)Wv, (const float4*)Wo,
        bq, bk, bv);
    roundx_h<<<((size_t)NR * DD / 4) / 256, 256>>>((const float4*)x);

    // 2) fused QKV projection -> fp16
    gemm_h<true><<<dim3(3072 / 128, NR / 128), 256, gemm_smem>>>(pX, pW3, pb3, pQKV, NR, 3072, DD);

    // 3) transpose V slice for ctx B-operand layout
    transpose_v<<<dim3(SS / 64, BB * HH), 256>>>(pQKV, pVT);

    // 4) raw causal scores (fp16 mma) -> attn region fp32
    scores_h<<<dim3(SS / 128, SS / 128, BB * HH), 256, scores_smem>>>(pQKV, attn);

    // 5) softmax per row (causal-predicated loads; zero-fills masked region)
    softmax_v8<<<BB * HH * SS, 256>>>(attn);

    // 6) ctx = attn @ V (fp16 mma) -> fp16 ctx
    ctx_h<<<dim3(SS / 128, BB * HH), 256, ctx_smem>>>(attn, pVT, pC);

    // 7) output projection (fp32 out)
    gemm_h<false><<<dim3(DD / 128, NR / 128), 256, gemm_smem>>>(pC, pWo, bo, out, NR, DD, DD);
}